// round 7
// baseline (speedup 1.0000x reference)
#include <cuda_runtime.h>
#include <math.h>
#include <stdint.h>

#define B_   16
#define N_   32768
#define S_   256
#define H_   256
#define NH_  8
#define DH_  32
#define DFF_ 1024
#define NC_  13

// ---------------- scratch (device globals; no allocations allowed) ----------
__device__ float g_sumxyz[B_*S_*3];
__device__ float g_sumfeat[B_*S_*4];
__device__ float g_cnt[B_*S_];
__device__ int   g_assign[B_*N_];
__device__ float g_x[B_*S_*H_];
__device__ float g_qkv[B_*S_*3*H_];
__device__ float g_attn[B_*S_*H_];
__device__ float g_tmp[B_*S_*H_];
__device__ float g_ff[B_*S_*DFF_];
__device__ float g_h1[B_*S_*H_];
__device__ float g_logits[B_*S_*NC_];

// ---------------- utils ----------
__device__ __forceinline__ float gelu_exact(float x) {
    return 0.5f * x * (1.0f + erff(x * 0.70710678118654752440f));
}

__device__ __forceinline__ uint32_t f2tf32(float x) {
    uint32_t r;
    asm("cvt.rna.tf32.f32 %0, %1;" : "=r"(r) : "f"(x));
    return r;
}

__device__ __forceinline__ void mma_tf32(float* d, const uint32_t* a,
                                         uint32_t b0, uint32_t b1) {
    asm volatile(
        "mma.sync.aligned.m16n8k8.row.col.f32.tf32.tf32.f32 "
        "{%0,%1,%2,%3},{%4,%5,%6,%7},{%8,%9},{%0,%1,%2,%3};"
        : "+f"(d[0]), "+f"(d[1]), "+f"(d[2]), "+f"(d[3])
        : "r"(a[0]), "r"(a[1]), "r"(a[2]), "r"(a[3]), "r"(b0), "r"(b1));
}

// ---------------- zero the segment accumulators ----------
__global__ void zero_kernel() {
    int t = blockIdx.x * blockDim.x + threadIdx.x;
    if (t < B_*S_*3) g_sumxyz[t]  = 0.f;
    if (t < B_*S_*4) g_sumfeat[t] = 0.f;
    if (t < B_*S_)   g_cnt[t]     = 0.f;
}

// ---------------- point -> seed argmin + block-local segment sums ----------
__global__ void assign_kernel(const float* __restrict__ xyz,
                              const float* __restrict__ feat,
                              const int*   __restrict__ seed_idx) {
    __shared__ float s_sx[S_], s_sy[S_], s_sz[S_], s_s2[S_];
    __shared__ float s_acc[S_*8];
    int b     = blockIdx.x >> 4;
    int chunk = blockIdx.x & 15;
    int tid   = threadIdx.x;

    {
        int idx = seed_idx[tid];
        float a0 = xyz[(size_t)(b*N_ + idx)*3 + 0];
        float a1 = xyz[(size_t)(b*N_ + idx)*3 + 1];
        float a2 = xyz[(size_t)(b*N_ + idx)*3 + 2];
        s_sx[tid] = a0; s_sy[tid] = a1; s_sz[tid] = a2;
        s_s2[tid] = (a0*a0 + a1*a1) + a2*a2;
    }
    #pragma unroll
    for (int i = 0; i < 8; i++) s_acc[tid + i*256] = 0.f;
    __syncthreads();

    for (int p = 0; p < 8; p++) {
        int n = chunk*2048 + p*256 + tid;
        size_t off = (size_t)(b*N_ + n);
        float x0 = xyz[off*3+0], x1 = xyz[off*3+1], x2 = xyz[off*3+2];
        float x2s = (x0*x0 + x1*x1) + x2*x2;
        // two independent argmin chains (halves) for ILP; merge keeps
        // first-occurrence-wins semantics.
        float bestA = INFINITY, bestB = INFINITY;
        int biA = 0, biB = 128;
        #pragma unroll 4
        for (int s = 0; s < 128; s++) {
            float da = x0 * s_sx[s];
            da = fmaf(x1, s_sy[s], da);
            da = fmaf(x2, s_sz[s], da);
            float d2a = (x2s + s_s2[s]) - 2.0f*da;
            float db = x0 * s_sx[s+128];
            db = fmaf(x1, s_sy[s+128], db);
            db = fmaf(x2, s_sz[s+128], db);
            float d2b = (x2s + s_s2[s+128]) - 2.0f*db;
            if (d2a < bestA) { bestA = d2a; biA = s; }
            if (d2b < bestB) { bestB = d2b; biB = s + 128; }
        }
        int bi = (bestB < bestA) ? biB : biA;
        g_assign[off] = bi;
        float4 f = ((const float4*)feat)[off];
        float* a = &s_acc[bi*8];
        atomicAdd(a+0, x0);  atomicAdd(a+1, x1);  atomicAdd(a+2, x2);
        atomicAdd(a+3, f.x); atomicAdd(a+4, f.y); atomicAdd(a+5, f.z); atomicAdd(a+6, f.w);
        atomicAdd(a+7, 1.0f);
    }
    __syncthreads();

    int s  = tid;
    int bs = b*S_ + s;
    atomicAdd(&g_sumxyz [bs*3+0], s_acc[s*8+0]);
    atomicAdd(&g_sumxyz [bs*3+1], s_acc[s*8+1]);
    atomicAdd(&g_sumxyz [bs*3+2], s_acc[s*8+2]);
    atomicAdd(&g_sumfeat[bs*4+0], s_acc[s*8+3]);
    atomicAdd(&g_sumfeat[bs*4+1], s_acc[s*8+4]);
    atomicAdd(&g_sumfeat[bs*4+2], s_acc[s*8+5]);
    atomicAdd(&g_sumfeat[bs*4+3], s_acc[s*8+6]);
    atomicAdd(&g_cnt[bs],         s_acc[s*8+7]);
}

// ---------------- superpoint features -> token projection ----------
__global__ void tokens_kernel(const float* __restrict__ xyz,
                              const int*   __restrict__ seed_idx,
                              const float* __restrict__ pw,
                              const float* __restrict__ pb) {
    __shared__ float sp[7];
    int bs  = blockIdx.x;
    int b   = bs >> 8, s = bs & 255;
    int tid = threadIdx.x;
    if (tid == 0) {
        float cnt   = g_cnt[bs];
        float denom = fmaxf(cnt, 1.0f);
        bool  empty = (cnt == 0.0f);
        int   idx   = seed_idx[s];
        #pragma unroll
        for (int c = 0; c < 3; c++) {
            float seedc = xyz[(size_t)(b*N_ + idx)*3 + c];
            sp[c] = empty ? seedc : g_sumxyz[bs*3+c] / denom;
        }
        #pragma unroll
        for (int c = 0; c < 4; c++)
            sp[3+c] = empty ? 0.f : g_sumfeat[bs*4+c] / denom;
    }
    __syncthreads();
    float acc = 0.f;
    #pragma unroll
    for (int i = 0; i < 7; i++) acc = fmaf(sp[i], pw[tid*7 + i], acc);
    g_x[(size_t)bs*H_ + tid] = acc + pb[tid];
}

// ---------------- tensor-core GEMM (3xTF32): C = epi(A @ W^T + bias) --------
// Inner loop is pass-major: each of the 3 precision passes sweeps all MT
// accumulators before the next pass, so consecutive MMAs hit different
// accumulators (no back-to-back RAW on acc).
// EPI: 0 = none, 1 = gelu, 2 = +residual
template<int TM, int TN, int WM, int WN, int THREADS, int MINCTA, int EPI>
__global__ void __launch_bounds__(THREADS, MINCTA)
sgemm_tc(const float* __restrict__ A, const float* __restrict__ W,
         const float* __restrict__ bias, const float* __restrict__ res,
         float* __restrict__ C, int M, int N, int K) {
    constexpr int KT = 8;
    constexpr int PA = TM + 8;
    constexpr int PB = TN + 8;
    constexpr int WCOLS = TN / WN;
    constexpr int MT = WM / 16;
    constexpr int NT = WN / 8;

    __shared__ uint32_t As_hi[2][KT][PA];
    __shared__ uint32_t As_lo[2][KT][PA];
    __shared__ uint32_t Ws_hi[2][KT][PB];
    __shared__ uint32_t Ws_lo[2][KT][PB];

    const int tid  = threadIdx.x;
    const int lane = tid & 31;
    const int wid  = tid >> 5;
    const int wrow = wid / WCOLS;
    const int wcol = wid % WCOLS;
    const int gr   = lane >> 2;          // 0..7
    const int ct   = lane & 3;           // 0..3
    const int bm   = blockIdx.y * TM;
    const int bn   = blockIdx.x * TN;

    // loader coords: thread -> (row, float4-within-KT)
    const int lr = tid >> 1;             // 0..TM-1 (TM*2 == THREADS)
    const int lc = (tid & 1) * 4;        // k base 0 or 4

    float acc[MT][NT][4];
    #pragma unroll
    for (int mt = 0; mt < MT; mt++)
        #pragma unroll
        for (int nt = 0; nt < NT; nt++)
            #pragma unroll
            for (int j = 0; j < 4; j++) acc[mt][nt][j] = 0.f;

    const float* Ap = A + (size_t)(bm + lr)*K + lc;
    const float* Wp = W + (size_t)(bn + lr)*K + lc;

    float4 av = *(const float4*)(Ap);
    float4 wv = *(const float4*)(Wp);

    auto stage = [&](int buf, float4 a, float4 w) {
        float af[4] = {a.x, a.y, a.z, a.w};
        float wf[4] = {w.x, w.y, w.z, w.w};
        #pragma unroll
        for (int j = 0; j < 4; j++) {
            uint32_t hi = f2tf32(af[j]);
            float lof = af[j] - __uint_as_float(hi);
            As_hi[buf][lc + j][lr] = hi;
            As_lo[buf][lc + j][lr] = f2tf32(lof);
        }
        #pragma unroll
        for (int j = 0; j < 4; j++) {
            uint32_t hi = f2tf32(wf[j]);
            float lof = wf[j] - __uint_as_float(hi);
            Ws_hi[buf][lc + j][lr] = hi;
            Ws_lo[buf][lc + j][lr] = f2tf32(lof);
        }
    };

    stage(0, av, wv);
    __syncthreads();

    const int nk = K / KT;
    for (int kt = 0; kt < nk; kt++) {
        const int buf = kt & 1;
        if (kt + 1 < nk) {
            av = *(const float4*)(Ap + (kt + 1)*KT);
            wv = *(const float4*)(Wp + (kt + 1)*KT);
        }

        uint32_t ah[MT][4], al[MT][4];
        #pragma unroll
        for (int mt = 0; mt < MT; mt++) {
            int m = wrow*WM + mt*16 + gr;
            ah[mt][0] = As_hi[buf][ct  ][m];
            ah[mt][1] = As_hi[buf][ct  ][m + 8];
            ah[mt][2] = As_hi[buf][ct+4][m];
            ah[mt][3] = As_hi[buf][ct+4][m + 8];
            al[mt][0] = As_lo[buf][ct  ][m];
            al[mt][1] = As_lo[buf][ct  ][m + 8];
            al[mt][2] = As_lo[buf][ct+4][m];
            al[mt][3] = As_lo[buf][ct+4][m + 8];
        }
        #pragma unroll
        for (int nt = 0; nt < NT; nt++) {
            int n = wcol*WN + nt*8 + gr;
            uint32_t bh0 = Ws_hi[buf][ct  ][n];
            uint32_t bh1 = Ws_hi[buf][ct+4][n];
            uint32_t bl0 = Ws_lo[buf][ct  ][n];
            uint32_t bl1 = Ws_lo[buf][ct+4][n];
            // pass-major: consecutive MMAs target different accumulators
            #pragma unroll
            for (int mt = 0; mt < MT; mt++)
                mma_tf32(acc[mt][nt], al[mt], bh0, bh1);   // lo*hi
            #pragma unroll
            for (int mt = 0; mt < MT; mt++)
                mma_tf32(acc[mt][nt], ah[mt], bl0, bl1);   // hi*lo
            #pragma unroll
            for (int mt = 0; mt < MT; mt++)
                mma_tf32(acc[mt][nt], ah[mt], bh0, bh1);   // hi*hi
        }

        if (kt + 1 < nk) stage(buf ^ 1, av, wv);
        __syncthreads();
    }

    // epilogue: C-frag layout m16n8: (gr, ct*2), (gr, ct*2+1), (+8 rows)
    #pragma unroll
    for (int mt = 0; mt < MT; mt++) {
        int row = bm + wrow*WM + mt*16 + gr;
        #pragma unroll
        for (int nt = 0; nt < NT; nt++) {
            int col = bn + wcol*WN + nt*8 + ct*2;
            float b0 = bias[col], b1 = bias[col + 1];
            float c0 = acc[mt][nt][0] + b0;
            float c1 = acc[mt][nt][1] + b1;
            float c2 = acc[mt][nt][2] + b0;
            float c3 = acc[mt][nt][3] + b1;
            if (EPI == 1) {
                c0 = gelu_exact(c0); c1 = gelu_exact(c1);
                c2 = gelu_exact(c2); c3 = gelu_exact(c3);
            }
            if (EPI == 2) {
                float2 r0 = *(const float2*)(res + (size_t)row*N + col);
                float2 r1 = *(const float2*)(res + (size_t)(row + 8)*N + col);
                c0 += r0.x; c1 += r0.y; c2 += r1.x; c3 += r1.y;
            }
            *(float2*)(C + (size_t)row*N + col)       = make_float2(c0, c1);
            *(float2*)(C + (size_t)(row + 8)*N + col) = make_float2(c2, c3);
        }
    }
}

// ---------------- attention: block = (b, head, half); 128 queries/block -----
__global__ void attention_kernel(const float* __restrict__ qkv,
                                 float* __restrict__ outp) {
    __shared__ float Ks[S_][DH_];
    int bid  = blockIdx.x;
    int half = bid & 1;
    int bh   = bid >> 1;
    int b    = bh >> 3, h = bh & 7;
    int tid  = threadIdx.x;                 // 0..127
    const float* base = qkv + (size_t)b*S_*(3*H_);
    #pragma unroll
    for (int r = tid; r < S_; r += 128) {
        const float4* kr = (const float4*)(base + (size_t)r*(3*H_) + H_ + h*DH_);
        float4* dst = (float4*)&Ks[r][0];
        #pragma unroll
        for (int i = 0; i < DH_/4; i++) dst[i] = kr[i];
    }
    int qrow = half*128 + tid;
    float q[DH_];
    {
        const float4* qr = (const float4*)(base + (size_t)qrow*(3*H_) + h*DH_);
        #pragma unroll
        for (int i = 0; i < DH_/4; i++) ((float4*)q)[i] = qr[i];
    }
    __syncthreads();

    const float scale = 0.17677669529663688110f;   // 1/sqrt(32)
    float m = -INFINITY, l = 0.f;
    float acc[DH_];
    #pragma unroll
    for (int d = 0; d < DH_; d++) acc[d] = 0.f;
    const float* vbase = base + 2*H_ + h*DH_;

    for (int j = 0; j < S_; j += 2) {
        float d0 = 0.f, d1 = 0.f, d2 = 0.f, d3 = 0.f;
        float e0 = 0.f, e1 = 0.f, e2 = 0.f, e3 = 0.f;
        #pragma unroll
        for (int i = 0; i < DH_/4; i++) {
            float4 k0 = ((const float4*)&Ks[j][0])[i];
            float4 k1 = ((const float4*)&Ks[j+1][0])[i];
            d0 = fmaf(q[4*i+0], k0.x, d0);
            d1 = fmaf(q[4*i+1], k0.y, d1);
            d2 = fmaf(q[4*i+2], k0.z, d2);
            d3 = fmaf(q[4*i+3], k0.w, d3);
            e0 = fmaf(q[4*i+0], k1.x, e0);
            e1 = fmaf(q[4*i+1], k1.y, e1);
            e2 = fmaf(q[4*i+2], k1.z, e2);
            e3 = fmaf(q[4*i+3], k1.w, e3);
        }
        float s0 = ((d0 + d1) + (d2 + d3)) * scale;
        float s1 = ((e0 + e1) + (e2 + e3)) * scale;
        float mn = fmaxf(m, fmaxf(s0, s1));
        float c  = __expf(m - mn);
        float p0 = __expf(s0 - mn);
        float p1 = __expf(s1 - mn);
        l = l*c + p0 + p1;
        const float4* v0 = (const float4*)(vbase + (size_t)j*(3*H_));
        const float4* v1 = (const float4*)(vbase + (size_t)(j+1)*(3*H_));
        #pragma unroll
        for (int i = 0; i < DH_/4; i++) {
            float4 a = v0[i], bq = v1[i];
            acc[i*4+0] = fmaf(acc[i*4+0], c, fmaf(p0, a.x, p1*bq.x));
            acc[i*4+1] = fmaf(acc[i*4+1], c, fmaf(p0, a.y, p1*bq.y));
            acc[i*4+2] = fmaf(acc[i*4+2], c, fmaf(p0, a.z, p1*bq.z));
            acc[i*4+3] = fmaf(acc[i*4+3], c, fmaf(p0, a.w, p1*bq.w));
        }
        m = mn;
    }
    float inv = 1.0f / l;
    float* orow = outp + (size_t)(b*S_ + qrow)*H_ + h*DH_;
    #pragma unroll
    for (int d = 0; d < DH_; d++) orow[d] = acc[d]*inv;
}

// ---------------- layernorm: single-pass (sum + sumsq), block per row -------
__global__ void layernorm_kernel(const float* __restrict__ in,
                                 const float* __restrict__ gw,
                                 const float* __restrict__ gb,
                                 float* __restrict__ outp) {
    __shared__ float red1[8], red2[8];
    __shared__ float s_mean, s_rstd;
    int row = blockIdx.x, tid = threadIdx.x;
    float v = in[(size_t)row*H_ + tid];
    float s1 = v, s2 = v*v;
    #pragma unroll
    for (int o = 16; o > 0; o >>= 1) {
        s1 += __shfl_xor_sync(0xffffffffu, s1, o);
        s2 += __shfl_xor_sync(0xffffffffu, s2, o);
    }
    if ((tid & 31) == 0) { red1[tid >> 5] = s1; red2[tid >> 5] = s2; }
    __syncthreads();
    if (tid == 0) {
        float t1 = 0.f, t2 = 0.f;
        #pragma unroll
        for (int i = 0; i < 8; i++) { t1 += red1[i]; t2 += red2[i]; }
        float mean = t1 * (1.0f/H_);
        float var  = t2 * (1.0f/H_) - mean*mean;
        s_mean = mean;
        s_rstd = rsqrtf(var + 1e-5f);
    }
    __syncthreads();
    outp[(size_t)row*H_ + tid] = (v - s_mean) * s_rstd * gw[tid] + gb[tid];
}

// ---------------- head2: logits (M x 13), one thread per output ----------
__global__ void head2_kernel(const float* __restrict__ X,
                             const float* __restrict__ W,
                             const float* __restrict__ bias) {
    int t = blockIdx.x * blockDim.x + threadIdx.x;
    if (t >= B_*S_*NC_) return;
    int row = t / NC_, c = t - row*NC_;
    const float4* x = (const float4*)(X + (size_t)row*H_);
    const float4* w = (const float4*)(W + (size_t)c*H_);
    float s0 = 0.f, s1 = 0.f, s2 = 0.f, s3 = 0.f;
    #pragma unroll 8
    for (int k = 0; k < H_/4; k++) {
        float4 xv = x[k], wv = w[k];
        s0 = fmaf(xv.x, wv.x, s0); s1 = fmaf(xv.y, wv.y, s1);
        s2 = fmaf(xv.z, wv.z, s2); s3 = fmaf(xv.w, wv.w, s3);
    }
    g_logits[t] = (s0+s1) + (s2+s3) + bias[c];
}

// ---------------- final gather to point logits ----------
__global__ void gather_kernel(float* __restrict__ out) {
    int t = blockIdx.x * blockDim.x + threadIdx.x;
    if (t >= B_*N_*NC_) return;
    int r = t / NC_;
    int c = t - r*NC_;
    int b = r >> 15;                // r / N_
    int a = g_assign[r];
    out[t] = g_logits[(b*S_ + a)*NC_ + c];
}

// ---------------- host launcher ----------
extern "C" void kernel_launch(void* const* d_in, const int* in_sizes, int n_in,
                              void* d_out, int out_size) {
    const float* xyz      = (const float*)d_in[0];
    const float* feat     = (const float*)d_in[1];
    const int*   seed_idx = (const int*)  d_in[2];
    const float* proj_w   = (const float*)d_in[3];
    const float* proj_b   = (const float*)d_in[4];
    const float* qkv_w    = (const float*)d_in[5];
    const float* qkv_b    = (const float*)d_in[6];
    const float* out_w    = (const float*)d_in[7];
    const float* out_b    = (const float*)d_in[8];
    const float* ln1_g    = (const float*)d_in[9];
    const float* ln1_b    = (const float*)d_in[10];
    const float* ln2_g    = (const float*)d_in[11];
    const float* ln2_b    = (const float*)d_in[12];
    const float* ff1_w    = (const float*)d_in[13];
    const float* ff1_b    = (const float*)d_in[14];
    const float* ff2_w    = (const float*)d_in[15];
    const float* ff2_b    = (const float*)d_in[16];
    const float* hln_g    = (const float*)d_in[17];
    const float* hln_b    = (const float*)d_in[18];
    const float* h1_w     = (const float*)d_in[19];
    const float* h1_b     = (const float*)d_in[20];
    const float* h2_w     = (const float*)d_in[21];
    const float* h2_b     = (const float*)d_in[22];
    float* out = (float*)d_out;

    float *p_x, *p_qkv, *p_attn, *p_tmp, *p_ff, *p_h1;
    cudaGetSymbolAddress((void**)&p_x,    g_x);
    cudaGetSymbolAddress((void**)&p_qkv,  g_qkv);
    cudaGetSymbolAddress((void**)&p_attn, g_attn);
    cudaGetSymbolAddress((void**)&p_tmp,  g_tmp);
    cudaGetSymbolAddress((void**)&p_ff,   g_ff);
    cudaGetSymbolAddress((void**)&p_h1,   g_h1);

    const int M = B_*S_;   // 4096

    zero_kernel<<<(B_*S_*4 + 255)/256, 256>>>();
    assign_kernel<<<B_*16, 256>>>(xyz, feat, seed_idx);
    tokens_kernel<<<B_*S_, 256>>>(xyz, seed_idx, proj_w, proj_b);

    for (int l = 0; l < 2; l++) {
        // QKV: M=4096, N=768, K=256 -> 128x128 tiles, grid 6x32=192
        sgemm_tc<128,128,64,32,256,2,0><<<dim3(3*H_/128, M/128), 256>>>(
            p_x, qkv_w + (size_t)l*3*H_*H_, qkv_b + l*3*H_, nullptr, p_qkv,
            M, 3*H_, H_);
        attention_kernel<<<B_*NH_*2, 128>>>(p_qkv, p_attn);
        // out-proj: N=256, K=256 -> 64x64 tiles (warp tile 64x16), grid 4x64
        sgemm_tc<64,64,64,16,128,4,2><<<dim3(H_/64, M/64), 128>>>(
            p_attn, out_w + (size_t)l*H_*H_, out_b + l*H_, p_x, p_tmp,
            M, H_, H_);
        layernorm_kernel<<<M, 256>>>(p_tmp, ln1_g + l*H_, ln1_b + l*H_, p_x);
        // FF1: N=1024, K=256 -> 128x128 tiles, grid 8x32=256
        sgemm_tc<128,128,64,32,256,2,1><<<dim3(DFF_/128, M/128), 256>>>(
            p_x, ff1_w + (size_t)l*DFF_*H_, ff1_b + l*DFF_, nullptr, p_ff,
            M, DFF_, H_);
        // FF2: N=256, K=1024 -> 64x64 tiles (warp tile 64x16)
        sgemm_tc<64,64,64,16,128,4,2><<<dim3(H_/64, M/64), 128>>>(
            p_ff, ff2_w + (size_t)l*H_*DFF_, ff2_b + l*H_, p_x, p_tmp,
            M, H_, DFF_);
        layernorm_kernel<<<M, 256>>>(p_tmp, ln2_g + l*H_, ln2_b + l*H_, p_x);
    }

    layernorm_kernel<<<M, 256>>>(p_x, hln_g, hln_b, p_tmp);
    sgemm_tc<64,64,64,16,128,4,1><<<dim3(H_/64, M/64), 128>>>(
        p_tmp, h1_w, h1_b, nullptr, p_h1, M, H_, H_);
    head2_kernel<<<(M*NC_ + 255)/256, 256>>>(p_h1, h2_w, h2_b);
    gather_kernel<<<(B_*N_*NC_ + 255)/256, 256>>>(out);
}

// round 8
// speedup vs baseline: 1.0057x; 1.0057x over previous
#include <cuda_runtime.h>
#include <math.h>
#include <stdint.h>

#define B_   16
#define N_   32768
#define S_   256
#define H_   256
#define NH_  8
#define DH_  32
#define DFF_ 1024
#define NC_  13

// ---------------- scratch (device globals; no allocations allowed) ----------
__device__ float g_sumxyz[B_*S_*3];
__device__ float g_sumfeat[B_*S_*4];
__device__ float g_cnt[B_*S_];
__device__ int   g_assign[B_*N_];
__device__ float g_x[B_*S_*H_];
__device__ float g_qkv[B_*S_*3*H_];
__device__ float g_attn[B_*S_*H_];
__device__ float g_tmp[B_*S_*H_];
__device__ float g_ff[B_*S_*DFF_];
__device__ float g_h1[B_*S_*H_];
__device__ float g_logits[B_*S_*NC_];

// ---------------- utils ----------
__device__ __forceinline__ float gelu_exact(float x) {
    return 0.5f * x * (1.0f + erff(x * 0.70710678118654752440f));
}

__device__ __forceinline__ uint32_t f2tf32(float x) {
    uint32_t r;
    asm("cvt.rna.tf32.f32 %0, %1;" : "=r"(r) : "f"(x));
    return r;
}

__device__ __forceinline__ void mma_tf32(float* d, const uint32_t* a,
                                         uint32_t b0, uint32_t b1) {
    asm volatile(
        "mma.sync.aligned.m16n8k8.row.col.f32.tf32.tf32.f32 "
        "{%0,%1,%2,%3},{%4,%5,%6,%7},{%8,%9},{%0,%1,%2,%3};"
        : "+f"(d[0]), "+f"(d[1]), "+f"(d[2]), "+f"(d[3])
        : "r"(a[0]), "r"(a[1]), "r"(a[2]), "r"(a[3]), "r"(b0), "r"(b1));
}

// ---------------- zero the segment accumulators ----------
__global__ void zero_kernel() {
    int t = blockIdx.x * blockDim.x + threadIdx.x;
    if (t < B_*S_*3) g_sumxyz[t]  = 0.f;
    if (t < B_*S_*4) g_sumfeat[t] = 0.f;
    if (t < B_*S_)   g_cnt[t]     = 0.f;
}

// ---------------- point -> seed argmin + block-local segment sums ----------
__global__ void assign_kernel(const float* __restrict__ xyz,
                              const float* __restrict__ feat,
                              const int*   __restrict__ seed_idx) {
    __shared__ float s_sx[S_], s_sy[S_], s_sz[S_], s_s2[S_];
    __shared__ float s_acc[S_*8];
    int b     = blockIdx.x >> 4;
    int chunk = blockIdx.x & 15;
    int tid   = threadIdx.x;

    {
        int idx = seed_idx[tid];
        float a0 = xyz[(size_t)(b*N_ + idx)*3 + 0];
        float a1 = xyz[(size_t)(b*N_ + idx)*3 + 1];
        float a2 = xyz[(size_t)(b*N_ + idx)*3 + 2];
        s_sx[tid] = a0; s_sy[tid] = a1; s_sz[tid] = a2;
        s_s2[tid] = (a0*a0 + a1*a1) + a2*a2;
    }
    #pragma unroll
    for (int i = 0; i < 8; i++) s_acc[tid + i*256] = 0.f;
    __syncthreads();

    for (int p = 0; p < 8; p++) {
        int n = chunk*2048 + p*256 + tid;
        size_t off = (size_t)(b*N_ + n);
        float x0 = xyz[off*3+0], x1 = xyz[off*3+1], x2 = xyz[off*3+2];
        float x2s = (x0*x0 + x1*x1) + x2*x2;
        float bestA = INFINITY, bestB = INFINITY;
        int biA = 0, biB = 128;
        #pragma unroll 4
        for (int s = 0; s < 128; s++) {
            float da = x0 * s_sx[s];
            da = fmaf(x1, s_sy[s], da);
            da = fmaf(x2, s_sz[s], da);
            float d2a = (x2s + s_s2[s]) - 2.0f*da;
            float db = x0 * s_sx[s+128];
            db = fmaf(x1, s_sy[s+128], db);
            db = fmaf(x2, s_sz[s+128], db);
            float d2b = (x2s + s_s2[s+128]) - 2.0f*db;
            if (d2a < bestA) { bestA = d2a; biA = s; }
            if (d2b < bestB) { bestB = d2b; biB = s + 128; }
        }
        int bi = (bestB < bestA) ? biB : biA;
        g_assign[off] = bi;
        float4 f = ((const float4*)feat)[off];
        float* a = &s_acc[bi*8];
        atomicAdd(a+0, x0);  atomicAdd(a+1, x1);  atomicAdd(a+2, x2);
        atomicAdd(a+3, f.x); atomicAdd(a+4, f.y); atomicAdd(a+5, f.z); atomicAdd(a+6, f.w);
        atomicAdd(a+7, 1.0f);
    }
    __syncthreads();

    int s  = tid;
    int bs = b*S_ + s;
    atomicAdd(&g_sumxyz [bs*3+0], s_acc[s*8+0]);
    atomicAdd(&g_sumxyz [bs*3+1], s_acc[s*8+1]);
    atomicAdd(&g_sumxyz [bs*3+2], s_acc[s*8+2]);
    atomicAdd(&g_sumfeat[bs*4+0], s_acc[s*8+3]);
    atomicAdd(&g_sumfeat[bs*4+1], s_acc[s*8+4]);
    atomicAdd(&g_sumfeat[bs*4+2], s_acc[s*8+5]);
    atomicAdd(&g_sumfeat[bs*4+3], s_acc[s*8+6]);
    atomicAdd(&g_cnt[bs],         s_acc[s*8+7]);
}

// ---------------- superpoint features -> token projection ----------
__global__ void tokens_kernel(const float* __restrict__ xyz,
                              const int*   __restrict__ seed_idx,
                              const float* __restrict__ pw,
                              const float* __restrict__ pb) {
    __shared__ float sp[7];
    int bs  = blockIdx.x;
    int b   = bs >> 8, s = bs & 255;
    int tid = threadIdx.x;
    if (tid == 0) {
        float cnt   = g_cnt[bs];
        float denom = fmaxf(cnt, 1.0f);
        bool  empty = (cnt == 0.0f);
        int   idx   = seed_idx[s];
        #pragma unroll
        for (int c = 0; c < 3; c++) {
            float seedc = xyz[(size_t)(b*N_ + idx)*3 + c];
            sp[c] = empty ? seedc : g_sumxyz[bs*3+c] / denom;
        }
        #pragma unroll
        for (int c = 0; c < 4; c++)
            sp[3+c] = empty ? 0.f : g_sumfeat[bs*4+c] / denom;
    }
    __syncthreads();
    float acc = 0.f;
    #pragma unroll
    for (int i = 0; i < 7; i++) acc = fmaf(sp[i], pw[tid*7 + i], acc);
    g_x[(size_t)bs*H_ + tid] = acc + pb[tid];
}

// ---------------- tensor-core GEMM (3xTF32): C = epi(A @ W^T + bias) --------
// Vectorized fragment SMEM layout: uint4 per (kgroup, row) packs
// {hi(k), hi(k+4), lo(k), lo(k+4)}. One LDS.128 per B fragment, two per
// A m-tile (hi+lo together). XOR swizzle (row ^ (kgroup<<1)) gives
// conflict-free quarter-warp phases.
// EPI: 0 = none, 1 = gelu, 2 = +residual
template<int TM, int TN, int WM, int WN, int THREADS, int MINCTA, int EPI>
__global__ void __launch_bounds__(THREADS, MINCTA)
sgemm_tc(const float* __restrict__ A, const float* __restrict__ W,
         const float* __restrict__ bias, const float* __restrict__ res,
         float* __restrict__ C, int M, int N, int K) {
    constexpr int KT = 8;
    constexpr int WCOLS = TN / WN;
    constexpr int MT = WM / 16;
    constexpr int NT = WN / 8;

    __shared__ uint4 As4[2][4][TM];
    __shared__ uint4 Ws4[2][4][TN];

    const int tid  = threadIdx.x;
    const int lane = tid & 31;
    const int wid  = tid >> 5;
    const int wrow = wid / WCOLS;
    const int wcol = wid % WCOLS;
    const int gr   = lane >> 2;          // 0..7
    const int ct   = lane & 3;           // 0..3
    const int bm   = blockIdx.y * TM;
    const int bn   = blockIdx.x * TN;

    // loader coords: thread -> (row, k-half)  (TM*2 == THREADS, TN == TM)
    const int lr = tid >> 1;             // 0..TM-1
    const int lc = (tid & 1) * 4;        // k base 0 or 4

    float acc[MT][NT][4];
    #pragma unroll
    for (int mt = 0; mt < MT; mt++)
        #pragma unroll
        for (int nt = 0; nt < NT; nt++)
            #pragma unroll
            for (int j = 0; j < 4; j++) acc[mt][nt][j] = 0.f;

    const float* Ap = A + (size_t)(bm + lr)*K + lc;
    const float* Wp = W + (size_t)(bn + lr)*K + lc;

    float4 av = *(const float4*)(Ap);
    float4 wv = *(const float4*)(Wp);

    auto stage = [&](int buf, float4 a, float4 w) {
        float af[4] = {a.x, a.y, a.z, a.w};
        float wf[4] = {w.x, w.y, w.z, w.w};
        #pragma unroll
        for (int j = 0; j < 4; j++) {
            int k = lc + j;              // 0..7
            int g = k & 3;
            int slot = k >> 2;           // 0 or 1
            uint32_t hi = f2tf32(af[j]);
            uint32_t lo = f2tf32(af[j] - __uint_as_float(hi));
            uint32_t* p = (uint32_t*)&As4[buf][g][lr ^ (g << 1)];
            p[slot] = hi; p[2 + slot] = lo;
            hi = f2tf32(wf[j]);
            lo = f2tf32(wf[j] - __uint_as_float(hi));
            p = (uint32_t*)&Ws4[buf][g][lr ^ (g << 1)];
            p[slot] = hi; p[2 + slot] = lo;
        }
    };

    stage(0, av, wv);
    __syncthreads();

    const int nk = K / KT;
    for (int kt = 0; kt < nk; kt++) {
        const int buf = kt & 1;
        if (kt + 1 < nk) {
            av = *(const float4*)(Ap + (kt + 1)*KT);
            wv = *(const float4*)(Wp + (kt + 1)*KT);
        }

        // A fragments: 2 LDS.128 per m-tile deliver hi+lo together
        uint32_t ah[MT][4], al[MT][4];
        #pragma unroll
        for (int mt = 0; mt < MT; mt++) {
            int m = wrow*WM + mt*16 + gr;
            uint4 va = As4[buf][ct][m ^ (ct << 1)];
            uint4 vb = As4[buf][ct][(m + 8) ^ (ct << 1)];
            ah[mt][0] = va.x; ah[mt][1] = vb.x; ah[mt][2] = va.y; ah[mt][3] = vb.y;
            al[mt][0] = va.z; al[mt][1] = vb.z; al[mt][2] = va.w; al[mt][3] = vb.w;
        }
        #pragma unroll
        for (int nt = 0; nt < NT; nt++) {
            int n = wcol*WN + nt*8 + gr;
            uint4 vw = Ws4[buf][ct][n ^ (ct << 1)];
            // pass-major: consecutive MMAs target different accumulators
            #pragma unroll
            for (int mt = 0; mt < MT; mt++)
                mma_tf32(acc[mt][nt], al[mt], vw.x, vw.y);   // lo*hi
            #pragma unroll
            for (int mt = 0; mt < MT; mt++)
                mma_tf32(acc[mt][nt], ah[mt], vw.z, vw.w);   // hi*lo
            #pragma unroll
            for (int mt = 0; mt < MT; mt++)
                mma_tf32(acc[mt][nt], ah[mt], vw.x, vw.y);   // hi*hi
        }

        if (kt + 1 < nk) stage(buf ^ 1, av, wv);
        __syncthreads();
    }

    // epilogue: C-frag layout m16n8: (gr, ct*2), (gr, ct*2+1), (+8 rows)
    #pragma unroll
    for (int mt = 0; mt < MT; mt++) {
        int row = bm + wrow*WM + mt*16 + gr;
        #pragma unroll
        for (int nt = 0; nt < NT; nt++) {
            int col = bn + wcol*WN + nt*8 + ct*2;
            float b0 = bias[col], b1 = bias[col + 1];
            float c0 = acc[mt][nt][0] + b0;
            float c1 = acc[mt][nt][1] + b1;
            float c2 = acc[mt][nt][2] + b0;
            float c3 = acc[mt][nt][3] + b1;
            if (EPI == 1) {
                c0 = gelu_exact(c0); c1 = gelu_exact(c1);
                c2 = gelu_exact(c2); c3 = gelu_exact(c3);
            }
            if (EPI == 2) {
                float2 r0 = *(const float2*)(res + (size_t)row*N + col);
                float2 r1 = *(const float2*)(res + (size_t)(row + 8)*N + col);
                c0 += r0.x; c1 += r0.y; c2 += r1.x; c3 += r1.y;
            }
            *(float2*)(C + (size_t)row*N + col)       = make_float2(c0, c1);
            *(float2*)(C + (size_t)(row + 8)*N + col) = make_float2(c2, c3);
        }
    }
}

// ---------------- attention: block = (b, head, half); 128 queries/block -----
__global__ void attention_kernel(const float* __restrict__ qkv,
                                 float* __restrict__ outp) {
    __shared__ float Ks[S_][DH_];
    int bid  = blockIdx.x;
    int half = bid & 1;
    int bh   = bid >> 1;
    int b    = bh >> 3, h = bh & 7;
    int tid  = threadIdx.x;                 // 0..127
    const float* base = qkv + (size_t)b*S_*(3*H_);
    #pragma unroll
    for (int r = tid; r < S_; r += 128) {
        const float4* kr = (const float4*)(base + (size_t)r*(3*H_) + H_ + h*DH_);
        float4* dst = (float4*)&Ks[r][0];
        #pragma unroll
        for (int i = 0; i < DH_/4; i++) dst[i] = kr[i];
    }
    int qrow = half*128 + tid;
    float q[DH_];
    {
        const float4* qr = (const float4*)(base + (size_t)qrow*(3*H_) + h*DH_);
        #pragma unroll
        for (int i = 0; i < DH_/4; i++) ((float4*)q)[i] = qr[i];
    }
    __syncthreads();

    const float scale = 0.17677669529663688110f;   // 1/sqrt(32)
    float m = -INFINITY, l = 0.f;
    float acc[DH_];
    #pragma unroll
    for (int d = 0; d < DH_; d++) acc[d] = 0.f;
    const float* vbase = base + 2*H_ + h*DH_;

    for (int j = 0; j < S_; j += 2) {
        float d0 = 0.f, d1 = 0.f, d2 = 0.f, d3 = 0.f;
        float e0 = 0.f, e1 = 0.f, e2 = 0.f, e3 = 0.f;
        #pragma unroll
        for (int i = 0; i < DH_/4; i++) {
            float4 k0 = ((const float4*)&Ks[j][0])[i];
            float4 k1 = ((const float4*)&Ks[j+1][0])[i];
            d0 = fmaf(q[4*i+0], k0.x, d0);
            d1 = fmaf(q[4*i+1], k0.y, d1);
            d2 = fmaf(q[4*i+2], k0.z, d2);
            d3 = fmaf(q[4*i+3], k0.w, d3);
            e0 = fmaf(q[4*i+0], k1.x, e0);
            e1 = fmaf(q[4*i+1], k1.y, e1);
            e2 = fmaf(q[4*i+2], k1.z, e2);
            e3 = fmaf(q[4*i+3], k1.w, e3);
        }
        float s0 = ((d0 + d1) + (d2 + d3)) * scale;
        float s1 = ((e0 + e1) + (e2 + e3)) * scale;
        float mn = fmaxf(m, fmaxf(s0, s1));
        float c  = __expf(m - mn);
        float p0 = __expf(s0 - mn);
        float p1 = __expf(s1 - mn);
        l = l*c + p0 + p1;
        const float4* v0 = (const float4*)(vbase + (size_t)j*(3*H_));
        const float4* v1 = (const float4*)(vbase + (size_t)(j+1)*(3*H_));
        #pragma unroll
        for (int i = 0; i < DH_/4; i++) {
            float4 a = v0[i], bq = v1[i];
            acc[i*4+0] = fmaf(acc[i*4+0], c, fmaf(p0, a.x, p1*bq.x));
            acc[i*4+1] = fmaf(acc[i*4+1], c, fmaf(p0, a.y, p1*bq.y));
            acc[i*4+2] = fmaf(acc[i*4+2], c, fmaf(p0, a.z, p1*bq.z));
            acc[i*4+3] = fmaf(acc[i*4+3], c, fmaf(p0, a.w, p1*bq.w));
        }
        m = mn;
    }
    float inv = 1.0f / l;
    float* orow = outp + (size_t)(b*S_ + qrow)*H_ + h*DH_;
    #pragma unroll
    for (int d = 0; d < DH_; d++) orow[d] = acc[d]*inv;
}

// ---------------- layernorm: single-pass (sum + sumsq), block per row -------
__global__ void layernorm_kernel(const float* __restrict__ in,
                                 const float* __restrict__ gw,
                                 const float* __restrict__ gb,
                                 float* __restrict__ outp) {
    __shared__ float red1[8], red2[8];
    __shared__ float s_mean, s_rstd;
    int row = blockIdx.x, tid = threadIdx.x;
    float v = in[(size_t)row*H_ + tid];
    float s1 = v, s2 = v*v;
    #pragma unroll
    for (int o = 16; o > 0; o >>= 1) {
        s1 += __shfl_xor_sync(0xffffffffu, s1, o);
        s2 += __shfl_xor_sync(0xffffffffu, s2, o);
    }
    if ((tid & 31) == 0) { red1[tid >> 5] = s1; red2[tid >> 5] = s2; }
    __syncthreads();
    if (tid == 0) {
        float t1 = 0.f, t2 = 0.f;
        #pragma unroll
        for (int i = 0; i < 8; i++) { t1 += red1[i]; t2 += red2[i]; }
        float mean = t1 * (1.0f/H_);
        float var  = t2 * (1.0f/H_) - mean*mean;
        s_mean = mean;
        s_rstd = rsqrtf(var + 1e-5f);
    }
    __syncthreads();
    outp[(size_t)row*H_ + tid] = (v - s_mean) * s_rstd * gw[tid] + gb[tid];
}

// ---------------- head2: logits (M x 13), one thread per output ----------
__global__ void head2_kernel(const float* __restrict__ X,
                             const float* __restrict__ W,
                             const float* __restrict__ bias) {
    int t = blockIdx.x * blockDim.x + threadIdx.x;
    if (t >= B_*S_*NC_) return;
    int row = t / NC_, c = t - row*NC_;
    const float4* x = (const float4*)(X + (size_t)row*H_);
    const float4* w = (const float4*)(W + (size_t)c*H_);
    float s0 = 0.f, s1 = 0.f, s2 = 0.f, s3 = 0.f;
    #pragma unroll 8
    for (int k = 0; k < H_/4; k++) {
        float4 xv = x[k], wv = w[k];
        s0 = fmaf(xv.x, wv.x, s0); s1 = fmaf(xv.y, wv.y, s1);
        s2 = fmaf(xv.z, wv.z, s2); s3 = fmaf(xv.w, wv.w, s3);
    }
    g_logits[t] = (s0+s1) + (s2+s3) + bias[c];
}

// ---------------- final gather to point logits ----------
__global__ void gather_kernel(float* __restrict__ out) {
    int t = blockIdx.x * blockDim.x + threadIdx.x;
    if (t >= B_*N_*NC_) return;
    int r = t / NC_;
    int c = t - r*NC_;
    int b = r >> 15;                // r / N_
    int a = g_assign[r];
    out[t] = g_logits[(b*S_ + a)*NC_ + c];
}

// ---------------- host launcher ----------
extern "C" void kernel_launch(void* const* d_in, const int* in_sizes, int n_in,
                              void* d_out, int out_size) {
    const float* xyz      = (const float*)d_in[0];
    const float* feat     = (const float*)d_in[1];
    const int*   seed_idx = (const int*)  d_in[2];
    const float* proj_w   = (const float*)d_in[3];
    const float* proj_b   = (const float*)d_in[4];
    const float* qkv_w    = (const float*)d_in[5];
    const float* qkv_b    = (const float*)d_in[6];
    const float* out_w    = (const float*)d_in[7];
    const float* out_b    = (const float*)d_in[8];
    const float* ln1_g    = (const float*)d_in[9];
    const float* ln1_b    = (const float*)d_in[10];
    const float* ln2_g    = (const float*)d_in[11];
    const float* ln2_b    = (const float*)d_in[12];
    const float* ff1_w    = (const float*)d_in[13];
    const float* ff1_b    = (const float*)d_in[14];
    const float* ff2_w    = (const float*)d_in[15];
    const float* ff2_b    = (const float*)d_in[16];
    const float* hln_g    = (const float*)d_in[17];
    const float* hln_b    = (const float*)d_in[18];
    const float* h1_w     = (const float*)d_in[19];
    const float* h1_b     = (const float*)d_in[20];
    const float* h2_w     = (const float*)d_in[21];
    const float* h2_b     = (const float*)d_in[22];
    float* out = (float*)d_out;

    float *p_x, *p_qkv, *p_attn, *p_tmp, *p_ff, *p_h1;
    cudaGetSymbolAddress((void**)&p_x,    g_x);
    cudaGetSymbolAddress((void**)&p_qkv,  g_qkv);
    cudaGetSymbolAddress((void**)&p_attn, g_attn);
    cudaGetSymbolAddress((void**)&p_tmp,  g_tmp);
    cudaGetSymbolAddress((void**)&p_ff,   g_ff);
    cudaGetSymbolAddress((void**)&p_h1,   g_h1);

    const int M = B_*S_;   // 4096

    zero_kernel<<<(B_*S_*4 + 255)/256, 256>>>();
    assign_kernel<<<B_*16, 256>>>(xyz, feat, seed_idx);
    tokens_kernel<<<B_*S_, 256>>>(xyz, seed_idx, proj_w, proj_b);

    for (int l = 0; l < 2; l++) {
        // QKV: M=4096, N=768, K=256 -> 128x128 tiles, grid 6x32=192
        sgemm_tc<128,128,64,32,256,2,0><<<dim3(3*H_/128, M/128), 256>>>(
            p_x, qkv_w + (size_t)l*3*H_*H_, qkv_b + l*3*H_, nullptr, p_qkv,
            M, 3*H_, H_);
        attention_kernel<<<B_*NH_*2, 128>>>(p_qkv, p_attn);
        // out-proj: N=256, K=256 -> 64x64 tiles (warp tile 64x16), grid 4x64
        sgemm_tc<64,64,64,16,128,4,2><<<dim3(H_/64, M/64), 128>>>(
            p_attn, out_w + (size_t)l*H_*H_, out_b + l*H_, p_x, p_tmp,
            M, H_, H_);
        layernorm_kernel<<<M, 256>>>(p_tmp, ln1_g + l*H_, ln1_b + l*H_, p_x);
        // FF1: N=1024, K=256 -> 128x128 tiles, grid 8x32=256
        sgemm_tc<128,128,64,32,256,2,1><<<dim3(DFF_/128, M/128), 256>>>(
            p_x, ff1_w + (size_t)l*DFF_*H_, ff1_b + l*DFF_, nullptr, p_ff,
            M, DFF_, H_);
        // FF2: N=256, K=1024 -> 64x64 tiles (warp tile 64x16)
        sgemm_tc<64,64,64,16,128,4,2><<<dim3(H_/64, M/64), 128>>>(
            p_ff, ff2_w + (size_t)l*H_*DFF_, ff2_b + l*H_, p_x, p_tmp,
            M, H_, DFF_);
        layernorm_kernel<<<M, 256>>>(p_tmp, ln2_g + l*H_, ln2_b + l*H_, p_x);
    }

    layernorm_kernel<<<M, 256>>>(p_x, hln_g, hln_b, p_tmp);
    sgemm_tc<64,64,64,16,128,4,1><<<dim3(H_/64, M/64), 128>>>(
        p_tmp, h1_w, h1_b, nullptr, p_h1, M, H_, H_);
    head2_kernel<<<(M*NC_ + 255)/256, 256>>>(p_h1, h2_w, h2_b);
    gather_kernel<<<(B_*N_*NC_ + 255)/256, 256>>>(out);
}

// round 9
// speedup vs baseline: 1.2410x; 1.2340x over previous
#include <cuda_runtime.h>
#include <cuda_bf16.h>
#include <math.h>
#include <stdint.h>

#define B_   16
#define N_   32768
#define S_   256
#define H_   256
#define NH_  8
#define DH_  32
#define DFF_ 1024
#define NC_  13

// ---------------- scratch (device globals; no allocations allowed) ----------
__device__ float g_sumxyz[B_*S_*3];
__device__ float g_sumfeat[B_*S_*4];
__device__ float g_cnt[B_*S_];
__device__ int   g_assign[B_*N_];
__device__ float g_x[B_*S_*H_];
__device__ float g_qkv[B_*S_*3*H_];
__device__ float g_attn[B_*S_*H_];
__device__ float g_tmp[B_*S_*H_];
__device__ float g_ff[B_*S_*DFF_];
__device__ float g_h1[B_*S_*H_];
__device__ float g_logits[B_*S_*NC_];

// ---------------- utils ----------
__device__ __forceinline__ float gelu_exact(float x) {
    return 0.5f * x * (1.0f + erff(x * 0.70710678118654752440f));
}

// split a float2 into packed bf16x2 hi and lo: x = hi + lo + O(2^-18 x)
__device__ __forceinline__ void bf16_split2(float fx, float fy,
                                            uint32_t& hi, uint32_t& lo) {
    __nv_bfloat162 h = __float22bfloat162_rn(make_float2(fx, fy));
    hi = *(uint32_t*)&h;
    float2 hf = __bfloat1622float2(h);
    __nv_bfloat162 l = __float22bfloat162_rn(make_float2(fx - hf.x, fy - hf.y));
    lo = *(uint32_t*)&l;
}

__device__ __forceinline__ void mma_bf16(float* d, const uint32_t* a,
                                         uint32_t b0, uint32_t b1) {
    asm volatile(
        "mma.sync.aligned.m16n8k16.row.col.f32.bf16.bf16.f32 "
        "{%0,%1,%2,%3},{%4,%5,%6,%7},{%8,%9},{%0,%1,%2,%3};"
        : "+f"(d[0]), "+f"(d[1]), "+f"(d[2]), "+f"(d[3])
        : "r"(a[0]), "r"(a[1]), "r"(a[2]), "r"(a[3]), "r"(b0), "r"(b1));
}

// ---------------- zero the segment accumulators ----------
__global__ void zero_kernel() {
    int t = blockIdx.x * blockDim.x + threadIdx.x;
    if (t < B_*S_*3) g_sumxyz[t]  = 0.f;
    if (t < B_*S_*4) g_sumfeat[t] = 0.f;
    if (t < B_*S_)   g_cnt[t]     = 0.f;
}

// ---------------- point -> seed argmin + block-local segment sums ----------
__global__ void assign_kernel(const float* __restrict__ xyz,
                              const float* __restrict__ feat,
                              const int*   __restrict__ seed_idx) {
    __shared__ float s_sx[S_], s_sy[S_], s_sz[S_], s_s2[S_];
    __shared__ float s_acc[S_*8];
    int b     = blockIdx.x >> 4;
    int chunk = blockIdx.x & 15;
    int tid   = threadIdx.x;

    {
        int idx = seed_idx[tid];
        float a0 = xyz[(size_t)(b*N_ + idx)*3 + 0];
        float a1 = xyz[(size_t)(b*N_ + idx)*3 + 1];
        float a2 = xyz[(size_t)(b*N_ + idx)*3 + 2];
        s_sx[tid] = a0; s_sy[tid] = a1; s_sz[tid] = a2;
        s_s2[tid] = (a0*a0 + a1*a1) + a2*a2;
    }
    #pragma unroll
    for (int i = 0; i < 8; i++) s_acc[tid + i*256] = 0.f;
    __syncthreads();

    for (int p = 0; p < 8; p++) {
        int n = chunk*2048 + p*256 + tid;
        size_t off = (size_t)(b*N_ + n);
        float x0 = xyz[off*3+0], x1 = xyz[off*3+1], x2 = xyz[off*3+2];
        float x2s = (x0*x0 + x1*x1) + x2*x2;
        float bestA = INFINITY, bestB = INFINITY;
        int biA = 0, biB = 128;
        #pragma unroll 4
        for (int s = 0; s < 128; s++) {
            float da = x0 * s_sx[s];
            da = fmaf(x1, s_sy[s], da);
            da = fmaf(x2, s_sz[s], da);
            float d2a = (x2s + s_s2[s]) - 2.0f*da;
            float db = x0 * s_sx[s+128];
            db = fmaf(x1, s_sy[s+128], db);
            db = fmaf(x2, s_sz[s+128], db);
            float d2b = (x2s + s_s2[s+128]) - 2.0f*db;
            if (d2a < bestA) { bestA = d2a; biA = s; }
            if (d2b < bestB) { bestB = d2b; biB = s + 128; }
        }
        int bi = (bestB < bestA) ? biB : biA;
        g_assign[off] = bi;
        float4 f = ((const float4*)feat)[off];
        float* a = &s_acc[bi*8];
        atomicAdd(a+0, x0);  atomicAdd(a+1, x1);  atomicAdd(a+2, x2);
        atomicAdd(a+3, f.x); atomicAdd(a+4, f.y); atomicAdd(a+5, f.z); atomicAdd(a+6, f.w);
        atomicAdd(a+7, 1.0f);
    }
    __syncthreads();

    int s  = tid;
    int bs = b*S_ + s;
    atomicAdd(&g_sumxyz [bs*3+0], s_acc[s*8+0]);
    atomicAdd(&g_sumxyz [bs*3+1], s_acc[s*8+1]);
    atomicAdd(&g_sumxyz [bs*3+2], s_acc[s*8+2]);
    atomicAdd(&g_sumfeat[bs*4+0], s_acc[s*8+3]);
    atomicAdd(&g_sumfeat[bs*4+1], s_acc[s*8+4]);
    atomicAdd(&g_sumfeat[bs*4+2], s_acc[s*8+5]);
    atomicAdd(&g_sumfeat[bs*4+3], s_acc[s*8+6]);
    atomicAdd(&g_cnt[bs],         s_acc[s*8+7]);
}

// ---------------- superpoint features -> token projection ----------
__global__ void tokens_kernel(const float* __restrict__ xyz,
                              const int*   __restrict__ seed_idx,
                              const float* __restrict__ pw,
                              const float* __restrict__ pb) {
    __shared__ float sp[7];
    int bs  = blockIdx.x;
    int b   = bs >> 8, s = bs & 255;
    int tid = threadIdx.x;
    if (tid == 0) {
        float cnt   = g_cnt[bs];
        float denom = fmaxf(cnt, 1.0f);
        bool  empty = (cnt == 0.0f);
        int   idx   = seed_idx[s];
        #pragma unroll
        for (int c = 0; c < 3; c++) {
            float seedc = xyz[(size_t)(b*N_ + idx)*3 + c];
            sp[c] = empty ? seedc : g_sumxyz[bs*3+c] / denom;
        }
        #pragma unroll
        for (int c = 0; c < 4; c++)
            sp[3+c] = empty ? 0.f : g_sumfeat[bs*4+c] / denom;
    }
    __syncthreads();
    float acc = 0.f;
    #pragma unroll
    for (int i = 0; i < 7; i++) acc = fmaf(sp[i], pw[tid*7 + i], acc);
    g_x[(size_t)bs*H_ + tid] = acc + pb[tid];
}

// ---------------- tensor-core GEMM (3xBF16, m16n8k16): C = epi(A@W^T + b) --
// fp32 operands are split in-kernel into bf16 hi + lo (packed bf16x2 per
// k-pair). 3 passes: al*bh + ah*bl + ah*bh; dropped lo*lo term ~2^-18.
// SMEM layout: [kpair 0..7][row] packed uint32, +8 pad (frag LDS
// conflict-free, same bank geometry as the verified tf32 version).
// KT=16. EPI: 0 = none, 1 = gelu, 2 = +residual
template<int TM, int TN, int WM, int WN, int THREADS, int MINCTA, int EPI>
__global__ void __launch_bounds__(THREADS, MINCTA)
sgemm_tc(const float* __restrict__ A, const float* __restrict__ W,
         const float* __restrict__ bias, const float* __restrict__ res,
         float* __restrict__ C, int M, int N, int K) {
    constexpr int KT = 16;
    constexpr int PA = TM + 8;
    constexpr int PB = TN + 8;
    constexpr int WCOLS = TN / WN;
    constexpr int MT = WM / 16;
    constexpr int NT = WN / 8;
    constexpr int NLD = TM * 4 / THREADS;   // float4 loads per thread per array (=2)

    __shared__ uint32_t As_hi[2][8][PA];
    __shared__ uint32_t As_lo[2][8][PA];
    __shared__ uint32_t Ws_hi[2][8][PB];
    __shared__ uint32_t Ws_lo[2][8][PB];

    const int tid  = threadIdx.x;
    const int lane = tid & 31;
    const int wid  = tid >> 5;
    const int wrow = wid / WCOLS;
    const int wcol = wid % WCOLS;
    const int gr   = lane >> 2;          // 0..7
    const int ct   = lane & 3;           // 0..3
    const int bm   = blockIdx.y * TM;
    const int bn   = blockIdx.x * TN;

    float acc[MT][NT][4];
    #pragma unroll
    for (int mt = 0; mt < MT; mt++)
        #pragma unroll
        for (int nt = 0; nt < NT; nt++)
            #pragma unroll
            for (int j = 0; j < 4; j++) acc[mt][nt][j] = 0.f;

    float4 av[NLD], wv[NLD];
    // loader: id = tid + t*THREADS -> row = id>>2, kq = id&3 (k = 4kq..4kq+3)
    #pragma unroll
    for (int t = 0; t < NLD; t++) {
        int id = tid + t*THREADS, r = id >> 2, kq = id & 3;
        av[t] = *(const float4*)(A + (size_t)(bm + r)*K + kq*4);
        wv[t] = *(const float4*)(W + (size_t)(bn + r)*K + kq*4);
    }

    auto stage = [&](int buf) {
        #pragma unroll
        for (int t = 0; t < NLD; t++) {
            int id = tid + t*THREADS, r = id >> 2, kq = id & 3;
            uint32_t h0, l0, h1, l1;
            bf16_split2(av[t].x, av[t].y, h0, l0);
            bf16_split2(av[t].z, av[t].w, h1, l1);
            As_hi[buf][2*kq  ][r] = h0;
            As_hi[buf][2*kq+1][r] = h1;
            As_lo[buf][2*kq  ][r] = l0;
            As_lo[buf][2*kq+1][r] = l1;
            bf16_split2(wv[t].x, wv[t].y, h0, l0);
            bf16_split2(wv[t].z, wv[t].w, h1, l1);
            Ws_hi[buf][2*kq  ][r] = h0;
            Ws_hi[buf][2*kq+1][r] = h1;
            Ws_lo[buf][2*kq  ][r] = l0;
            Ws_lo[buf][2*kq+1][r] = l1;
        }
    };

    stage(0);
    __syncthreads();

    const int nk = K / KT;
    for (int kt = 0; kt < nk; kt++) {
        const int buf = kt & 1;
        if (kt + 1 < nk) {
            int k0 = (kt + 1) * KT;
            #pragma unroll
            for (int t = 0; t < NLD; t++) {
                int id = tid + t*THREADS, r = id >> 2, kq = id & 3;
                av[t] = *(const float4*)(A + (size_t)(bm + r)*K + k0 + kq*4);
                wv[t] = *(const float4*)(W + (size_t)(bn + r)*K + k0 + kq*4);
            }
        }

        // A fragments (m16n8k16): a0/a1 at kpair ct, a2/a3 at kpair ct+4
        uint32_t ah[MT][4], al[MT][4];
        #pragma unroll
        for (int mt = 0; mt < MT; mt++) {
            int m = wrow*WM + mt*16 + gr;
            ah[mt][0] = As_hi[buf][ct  ][m];
            ah[mt][1] = As_hi[buf][ct  ][m + 8];
            ah[mt][2] = As_hi[buf][ct+4][m];
            ah[mt][3] = As_hi[buf][ct+4][m + 8];
            al[mt][0] = As_lo[buf][ct  ][m];
            al[mt][1] = As_lo[buf][ct  ][m + 8];
            al[mt][2] = As_lo[buf][ct+4][m];
            al[mt][3] = As_lo[buf][ct+4][m + 8];
        }
        #pragma unroll
        for (int nt = 0; nt < NT; nt++) {
            int n = wcol*WN + nt*8 + gr;
            uint32_t bh0 = Ws_hi[buf][ct  ][n];
            uint32_t bh1 = Ws_hi[buf][ct+4][n];
            uint32_t bl0 = Ws_lo[buf][ct  ][n];
            uint32_t bl1 = Ws_lo[buf][ct+4][n];
            #pragma unroll
            for (int mt = 0; mt < MT; mt++) {
                mma_bf16(acc[mt][nt], al[mt], bh0, bh1);   // lo*hi
                mma_bf16(acc[mt][nt], ah[mt], bl0, bl1);   // hi*lo
                mma_bf16(acc[mt][nt], ah[mt], bh0, bh1);   // hi*hi
            }
        }

        if (kt + 1 < nk) stage(buf ^ 1);
        __syncthreads();
    }

    // epilogue: C-frag m16n8: c0,c1 at (gr, ct*2..+1), c2,c3 at (gr+8, same)
    #pragma unroll
    for (int mt = 0; mt < MT; mt++) {
        int row = bm + wrow*WM + mt*16 + gr;
        #pragma unroll
        for (int nt = 0; nt < NT; nt++) {
            int col = bn + wcol*WN + nt*8 + ct*2;
            float b0 = bias[col], b1 = bias[col + 1];
            float c0 = acc[mt][nt][0] + b0;
            float c1 = acc[mt][nt][1] + b1;
            float c2 = acc[mt][nt][2] + b0;
            float c3 = acc[mt][nt][3] + b1;
            if (EPI == 1) {
                c0 = gelu_exact(c0); c1 = gelu_exact(c1);
                c2 = gelu_exact(c2); c3 = gelu_exact(c3);
            }
            if (EPI == 2) {
                float2 r0 = *(const float2*)(res + (size_t)row*N + col);
                float2 r1 = *(const float2*)(res + (size_t)(row + 8)*N + col);
                c0 += r0.x; c1 += r0.y; c2 += r1.x; c3 += r1.y;
            }
            *(float2*)(C + (size_t)row*N + col)       = make_float2(c0, c1);
            *(float2*)(C + (size_t)(row + 8)*N + col) = make_float2(c2, c3);
        }
    }
}

// ---------------- attention: block = (b, head, half); 128 queries/block -----
__global__ void attention_kernel(const float* __restrict__ qkv,
                                 float* __restrict__ outp) {
    __shared__ float Ks[S_][DH_];
    int bid  = blockIdx.x;
    int half = bid & 1;
    int bh   = bid >> 1;
    int b    = bh >> 3, h = bh & 7;
    int tid  = threadIdx.x;                 // 0..127
    const float* base = qkv + (size_t)b*S_*(3*H_);
    #pragma unroll
    for (int r = tid; r < S_; r += 128) {
        const float4* kr = (const float4*)(base + (size_t)r*(3*H_) + H_ + h*DH_);
        float4* dst = (float4*)&Ks[r][0];
        #pragma unroll
        for (int i = 0; i < DH_/4; i++) dst[i] = kr[i];
    }
    int qrow = half*128 + tid;
    float q[DH_];
    {
        const float4* qr = (const float4*)(base + (size_t)qrow*(3*H_) + h*DH_);
        #pragma unroll
        for (int i = 0; i < DH_/4; i++) ((float4*)q)[i] = qr[i];
    }
    __syncthreads();

    const float scale = 0.17677669529663688110f;   // 1/sqrt(32)
    float m = -INFINITY, l = 0.f;
    float acc[DH_];
    #pragma unroll
    for (int d = 0; d < DH_; d++) acc[d] = 0.f;
    const float* vbase = base + 2*H_ + h*DH_;

    for (int j = 0; j < S_; j += 2) {
        float d0 = 0.f, d1 = 0.f, d2 = 0.f, d3 = 0.f;
        float e0 = 0.f, e1 = 0.f, e2 = 0.f, e3 = 0.f;
        #pragma unroll
        for (int i = 0; i < DH_/4; i++) {
            float4 k0 = ((const float4*)&Ks[j][0])[i];
            float4 k1 = ((const float4*)&Ks[j+1][0])[i];
            d0 = fmaf(q[4*i+0], k0.x, d0);
            d1 = fmaf(q[4*i+1], k0.y, d1);
            d2 = fmaf(q[4*i+2], k0.z, d2);
            d3 = fmaf(q[4*i+3], k0.w, d3);
            e0 = fmaf(q[4*i+0], k1.x, e0);
            e1 = fmaf(q[4*i+1], k1.y, e1);
            e2 = fmaf(q[4*i+2], k1.z, e2);
            e3 = fmaf(q[4*i+3], k1.w, e3);
        }
        float s0 = ((d0 + d1) + (d2 + d3)) * scale;
        float s1 = ((e0 + e1) + (e2 + e3)) * scale;
        float mn = fmaxf(m, fmaxf(s0, s1));
        float c  = __expf(m - mn);
        float p0 = __expf(s0 - mn);
        float p1 = __expf(s1 - mn);
        l = l*c + p0 + p1;
        const float4* v0 = (const float4*)(vbase + (size_t)j*(3*H_));
        const float4* v1 = (const float4*)(vbase + (size_t)(j+1)*(3*H_));
        #pragma unroll
        for (int i = 0; i < DH_/4; i++) {
            float4 a = v0[i], bq = v1[i];
            acc[i*4+0] = fmaf(acc[i*4+0], c, fmaf(p0, a.x, p1*bq.x));
            acc[i*4+1] = fmaf(acc[i*4+1], c, fmaf(p0, a.y, p1*bq.y));
            acc[i*4+2] = fmaf(acc[i*4+2], c, fmaf(p0, a.z, p1*bq.z));
            acc[i*4+3] = fmaf(acc[i*4+3], c, fmaf(p0, a.w, p1*bq.w));
        }
        m = mn;
    }
    float inv = 1.0f / l;
    float* orow = outp + (size_t)(b*S_ + qrow)*H_ + h*DH_;
    #pragma unroll
    for (int d = 0; d < DH_; d++) orow[d] = acc[d]*inv;
}

// ---------------- layernorm: single-pass (sum + sumsq), block per row -------
__global__ void layernorm_kernel(const float* __restrict__ in,
                                 const float* __restrict__ gw,
                                 const float* __restrict__ gb,
                                 float* __restrict__ outp) {
    __shared__ float red1[8], red2[8];
    __shared__ float s_mean, s_rstd;
    int row = blockIdx.x, tid = threadIdx.x;
    float v = in[(size_t)row*H_ + tid];
    float s1 = v, s2 = v*v;
    #pragma unroll
    for (int o = 16; o > 0; o >>= 1) {
        s1 += __shfl_xor_sync(0xffffffffu, s1, o);
        s2 += __shfl_xor_sync(0xffffffffu, s2, o);
    }
    if ((tid & 31) == 0) { red1[tid >> 5] = s1; red2[tid >> 5] = s2; }
    __syncthreads();
    if (tid == 0) {
        float t1 = 0.f, t2 = 0.f;
        #pragma unroll
        for (int i = 0; i < 8; i++) { t1 += red1[i]; t2 += red2[i]; }
        float mean = t1 * (1.0f/H_);
        float var  = t2 * (1.0f/H_) - mean*mean;
        s_mean = mean;
        s_rstd = rsqrtf(var + 1e-5f);
    }
    __syncthreads();
    outp[(size_t)row*H_ + tid] = (v - s_mean) * s_rstd * gw[tid] + gb[tid];
}

// ---------------- head2: logits (M x 13), one thread per output ----------
__global__ void head2_kernel(const float* __restrict__ X,
                             const float* __restrict__ W,
                             const float* __restrict__ bias) {
    int t = blockIdx.x * blockDim.x + threadIdx.x;
    if (t >= B_*S_*NC_) return;
    int row = t / NC_, c = t - row*NC_;
    const float4* x = (const float4*)(X + (size_t)row*H_);
    const float4* w = (const float4*)(W + (size_t)c*H_);
    float s0 = 0.f, s1 = 0.f, s2 = 0.f, s3 = 0.f;
    #pragma unroll 8
    for (int k = 0; k < H_/4; k++) {
        float4 xv = x[k], wv = w[k];
        s0 = fmaf(xv.x, wv.x, s0); s1 = fmaf(xv.y, wv.y, s1);
        s2 = fmaf(xv.z, wv.z, s2); s3 = fmaf(xv.w, wv.w, s3);
    }
    g_logits[t] = (s0+s1) + (s2+s3) + bias[c];
}

// ---------------- final gather to point logits ----------
__global__ void gather_kernel(float* __restrict__ out) {
    int t = blockIdx.x * blockDim.x + threadIdx.x;
    if (t >= B_*N_*NC_) return;
    int r = t / NC_;
    int c = t - r*NC_;
    int b = r >> 15;                // r / N_
    int a = g_assign[r];
    out[t] = g_logits[(b*S_ + a)*NC_ + c];
}

// ---------------- host launcher ----------
extern "C" void kernel_launch(void* const* d_in, const int* in_sizes, int n_in,
                              void* d_out, int out_size) {
    const float* xyz      = (const float*)d_in[0];
    const float* feat     = (const float*)d_in[1];
    const int*   seed_idx = (const int*)  d_in[2];
    const float* proj_w   = (const float*)d_in[3];
    const float* proj_b   = (const float*)d_in[4];
    const float* qkv_w    = (const float*)d_in[5];
    const float* qkv_b    = (const float*)d_in[6];
    const float* out_w    = (const float*)d_in[7];
    const float* out_b    = (const float*)d_in[8];
    const float* ln1_g    = (const float*)d_in[9];
    const float* ln1_b    = (const float*)d_in[10];
    const float* ln2_g    = (const float*)d_in[11];
    const float* ln2_b    = (const float*)d_in[12];
    const float* ff1_w    = (const float*)d_in[13];
    const float* ff1_b    = (const float*)d_in[14];
    const float* ff2_w    = (const float*)d_in[15];
    const float* ff2_b    = (const float*)d_in[16];
    const float* hln_g    = (const float*)d_in[17];
    const float* hln_b    = (const float*)d_in[18];
    const float* h1_w     = (const float*)d_in[19];
    const float* h1_b     = (const float*)d_in[20];
    const float* h2_w     = (const float*)d_in[21];
    const float* h2_b     = (const float*)d_in[22];
    float* out = (float*)d_out;

    float *p_x, *p_qkv, *p_attn, *p_tmp, *p_ff, *p_h1;
    cudaGetSymbolAddress((void**)&p_x,    g_x);
    cudaGetSymbolAddress((void**)&p_qkv,  g_qkv);
    cudaGetSymbolAddress((void**)&p_attn, g_attn);
    cudaGetSymbolAddress((void**)&p_tmp,  g_tmp);
    cudaGetSymbolAddress((void**)&p_ff,   g_ff);
    cudaGetSymbolAddress((void**)&p_h1,   g_h1);

    const int M = B_*S_;   // 4096

    zero_kernel<<<(B_*S_*4 + 255)/256, 256>>>();
    assign_kernel<<<B_*16, 256>>>(xyz, feat, seed_idx);
    tokens_kernel<<<B_*S_, 256>>>(xyz, seed_idx, proj_w, proj_b);

    for (int l = 0; l < 2; l++) {
        // QKV: M=4096, N=768, K=256 -> 128x128 tiles, grid 6x32=192
        sgemm_tc<128,128,64,32,256,2,0><<<dim3(3*H_/128, M/128), 256>>>(
            p_x, qkv_w + (size_t)l*3*H_*H_, qkv_b + l*3*H_, nullptr, p_qkv,
            M, 3*H_, H_);
        attention_kernel<<<B_*NH_*2, 128>>>(p_qkv, p_attn);
        // out-proj: N=256, K=256 -> 64x64 tiles, grid 4x64=256
        sgemm_tc<64,64,32,32,128,4,2><<<dim3(H_/64, M/64), 128>>>(
            p_attn, out_w + (size_t)l*H_*H_, out_b + l*H_, p_x, p_tmp,
            M, H_, H_);
        layernorm_kernel<<<M, 256>>>(p_tmp, ln1_g + l*H_, ln1_b + l*H_, p_x);
        // FF1: N=1024, K=256 -> 128x128 tiles, grid 8x32=256
        sgemm_tc<128,128,64,32,256,2,1><<<dim3(DFF_/128, M/128), 256>>>(
            p_x, ff1_w + (size_t)l*DFF_*H_, ff1_b + l*DFF_, nullptr, p_ff,
            M, DFF_, H_);
        // FF2: N=256, K=1024 -> 64x64 tiles
        sgemm_tc<64,64,32,32,128,4,2><<<dim3(H_/64, M/64), 128>>>(
            p_ff, ff2_w + (size_t)l*H_*DFF_, ff2_b + l*H_, p_x, p_tmp,
            M, H_, DFF_);
        layernorm_kernel<<<M, 256>>>(p_tmp, ln2_g + l*H_, ln2_b + l*H_, p_x);
    }

    layernorm_kernel<<<M, 256>>>(p_x, hln_g, hln_b, p_tmp);
    sgemm_tc<64,64,32,32,128,4,1><<<dim3(H_/64, M/64), 128>>>(
        p_tmp, h1_w, h1_b, nullptr, p_h1, M, H_, H_);
    head2_kernel<<<(M*NC_ + 255)/256, 256>>>(p_h1, h2_w, h2_b);
    gather_kernel<<<(B_*N_*NC_ + 255)/256, 256>>>(out);
}

// round 10
// speedup vs baseline: 1.2746x; 1.0270x over previous
#include <cuda_runtime.h>
#include <cuda_bf16.h>
#include <math.h>
#include <stdint.h>

#define B_   16
#define N_   32768
#define S_   256
#define H_   256
#define NH_  8
#define DH_  32
#define DFF_ 1024
#define NC_  13

// ---------------- scratch (device globals; no allocations allowed) ----------
__device__ float g_sumxyz[B_*S_*3];
__device__ float g_sumfeat[B_*S_*4];
__device__ float g_cnt[B_*S_];
__device__ int   g_assign[B_*N_];
__device__ float g_x[B_*S_*H_];
__device__ float g_qkv[B_*S_*3*H_];
__device__ float g_attn[B_*S_*H_];
__device__ float g_tmp[B_*S_*H_];
__device__ float g_ff[B_*S_*DFF_];
__device__ float g_h1[B_*S_*H_];
__device__ float g_logits[B_*S_*NC_];

// ---------------- utils ----------
__device__ __forceinline__ float gelu_exact(float x) {
    return 0.5f * x * (1.0f + erff(x * 0.70710678118654752440f));
}

// split a float2 into packed bf16x2 hi and lo: x = hi + lo + O(2^-18 x)
__device__ __forceinline__ void bf16_split2(float fx, float fy,
                                            uint32_t& hi, uint32_t& lo) {
    __nv_bfloat162 h = __float22bfloat162_rn(make_float2(fx, fy));
    hi = *(uint32_t*)&h;
    float2 hf = __bfloat1622float2(h);
    __nv_bfloat162 l = __float22bfloat162_rn(make_float2(fx - hf.x, fy - hf.y));
    lo = *(uint32_t*)&l;
}

__device__ __forceinline__ void mma_bf16(float* d, const uint32_t* a,
                                         uint32_t b0, uint32_t b1) {
    asm volatile(
        "mma.sync.aligned.m16n8k16.row.col.f32.bf16.bf16.f32 "
        "{%0,%1,%2,%3},{%4,%5,%6,%7},{%8,%9},{%0,%1,%2,%3};"
        : "+f"(d[0]), "+f"(d[1]), "+f"(d[2]), "+f"(d[3])
        : "r"(a[0]), "r"(a[1]), "r"(a[2]), "r"(a[3]), "r"(b0), "r"(b1));
}

// ---------------- zero the segment accumulators ----------
__global__ void zero_kernel() {
    int t = blockIdx.x * blockDim.x + threadIdx.x;
    if (t < B_*S_*3) g_sumxyz[t]  = 0.f;
    if (t < B_*S_*4) g_sumfeat[t] = 0.f;
    if (t < B_*S_)   g_cnt[t]     = 0.f;
}

// ---------------- point -> seed argmin + block-local segment sums ----------
// 4-point register blocking: each seed LDS.128 is reused by 4 points.
__global__ void assign_kernel(const float* __restrict__ xyz,
                              const float* __restrict__ feat,
                              const int*   __restrict__ seed_idx) {
    __shared__ float4 s_seed[S_];
    __shared__ float s_acc[S_*8];
    int b     = blockIdx.x >> 4;
    int chunk = blockIdx.x & 15;
    int tid   = threadIdx.x;

    {
        int idx = seed_idx[tid];
        float a0 = xyz[(size_t)(b*N_ + idx)*3 + 0];
        float a1 = xyz[(size_t)(b*N_ + idx)*3 + 1];
        float a2 = xyz[(size_t)(b*N_ + idx)*3 + 2];
        s_seed[tid] = make_float4(a0, a1, a2, (a0*a0 + a1*a1) + a2*a2);
    }
    #pragma unroll
    for (int i = 0; i < 8; i++) s_acc[tid + i*256] = 0.f;
    __syncthreads();

    for (int pp = 0; pp < 2; pp++) {
        int n0 = chunk*2048 + pp*1024;
        float px[4], py[4], pz[4], pw[4];
        #pragma unroll
        for (int i = 0; i < 4; i++) {
            size_t off = (size_t)(b*N_ + n0 + i*256 + tid);
            px[i] = xyz[off*3+0];
            py[i] = xyz[off*3+1];
            pz[i] = xyz[off*3+2];
            pw[i] = (px[i]*px[i] + py[i]*py[i]) + pz[i]*pz[i];
        }
        float best[4] = {INFINITY, INFINITY, INFINITY, INFINITY};
        int   bi[4]   = {0, 0, 0, 0};
        #pragma unroll 2
        for (int s = 0; s < S_; s++) {
            float4 sd = s_seed[s];
            #pragma unroll
            for (int i = 0; i < 4; i++) {
                float d = px[i] * sd.x;
                d = fmaf(py[i], sd.y, d);
                d = fmaf(pz[i], sd.z, d);
                float d2 = (pw[i] + sd.w) - 2.0f*d;
                if (d2 < best[i]) { best[i] = d2; bi[i] = s; }  // first wins
            }
        }
        #pragma unroll
        for (int i = 0; i < 4; i++) {
            size_t off = (size_t)(b*N_ + n0 + i*256 + tid);
            g_assign[off] = bi[i];
            float4 f = ((const float4*)feat)[off];
            float* a = &s_acc[bi[i]*8];
            atomicAdd(a+0, px[i]); atomicAdd(a+1, py[i]); atomicAdd(a+2, pz[i]);
            atomicAdd(a+3, f.x);   atomicAdd(a+4, f.y);
            atomicAdd(a+5, f.z);   atomicAdd(a+6, f.w);
            atomicAdd(a+7, 1.0f);
        }
    }
    __syncthreads();

    int s  = tid;
    int bs = b*S_ + s;
    atomicAdd(&g_sumxyz [bs*3+0], s_acc[s*8+0]);
    atomicAdd(&g_sumxyz [bs*3+1], s_acc[s*8+1]);
    atomicAdd(&g_sumxyz [bs*3+2], s_acc[s*8+2]);
    atomicAdd(&g_sumfeat[bs*4+0], s_acc[s*8+3]);
    atomicAdd(&g_sumfeat[bs*4+1], s_acc[s*8+4]);
    atomicAdd(&g_sumfeat[bs*4+2], s_acc[s*8+5]);
    atomicAdd(&g_sumfeat[bs*4+3], s_acc[s*8+6]);
    atomicAdd(&g_cnt[bs],         s_acc[s*8+7]);
}

// ---------------- superpoint features -> token projection ----------
__global__ void tokens_kernel(const float* __restrict__ xyz,
                              const int*   __restrict__ seed_idx,
                              const float* __restrict__ pw,
                              const float* __restrict__ pb) {
    __shared__ float sp[7];
    int bs  = blockIdx.x;
    int b   = bs >> 8, s = bs & 255;
    int tid = threadIdx.x;
    if (tid == 0) {
        float cnt   = g_cnt[bs];
        float denom = fmaxf(cnt, 1.0f);
        bool  empty = (cnt == 0.0f);
        int   idx   = seed_idx[s];
        #pragma unroll
        for (int c = 0; c < 3; c++) {
            float seedc = xyz[(size_t)(b*N_ + idx)*3 + c];
            sp[c] = empty ? seedc : g_sumxyz[bs*3+c] / denom;
        }
        #pragma unroll
        for (int c = 0; c < 4; c++)
            sp[3+c] = empty ? 0.f : g_sumfeat[bs*4+c] / denom;
    }
    __syncthreads();
    float acc = 0.f;
    #pragma unroll
    for (int i = 0; i < 7; i++) acc = fmaf(sp[i], pw[tid*7 + i], acc);
    g_x[(size_t)bs*H_ + tid] = acc + pb[tid];
}

// ---------------- tensor-core GEMM (3xBF16, m16n8k16): C = epi(A@W^T + b) --
// fp32 operands split in-kernel into bf16 hi + lo (packed bf16x2 per k-pair),
// 3 passes: al*bh + ah*bl + ah*bh (dropped lo*lo ~2^-18).
// KT=16, double-buffered, +8 pad => conflict-free fragment LDS.
// EPI: 0 = none, 1 = gelu, 2 = +residual
template<int TM, int TN, int WM, int WN, int THREADS, int MINCTA, int EPI>
__global__ void __launch_bounds__(THREADS, MINCTA)
sgemm_tc(const float* __restrict__ A, const float* __restrict__ W,
         const float* __restrict__ bias, const float* __restrict__ res,
         float* __restrict__ C, int M, int N, int K) {
    constexpr int KT = 16;
    constexpr int PA = TM + 8;
    constexpr int PB = TN + 8;
    constexpr int WCOLS = TN / WN;
    constexpr int MT = WM / 16;
    constexpr int NT = WN / 8;
    constexpr int NLA = TM * 4 / THREADS;   // A float4 loads per thread
    constexpr int NLB = TN * 4 / THREADS;   // W float4 loads per thread

    __shared__ uint32_t As_hi[2][8][PA];
    __shared__ uint32_t As_lo[2][8][PA];
    __shared__ uint32_t Ws_hi[2][8][PB];
    __shared__ uint32_t Ws_lo[2][8][PB];

    const int tid  = threadIdx.x;
    const int lane = tid & 31;
    const int wid  = tid >> 5;
    const int wrow = wid / WCOLS;
    const int wcol = wid % WCOLS;
    const int gr   = lane >> 2;          // 0..7
    const int ct   = lane & 3;           // 0..3
    const int bm   = blockIdx.y * TM;
    const int bn   = blockIdx.x * TN;

    float acc[MT][NT][4];
    #pragma unroll
    for (int mt = 0; mt < MT; mt++)
        #pragma unroll
        for (int nt = 0; nt < NT; nt++)
            #pragma unroll
            for (int j = 0; j < 4; j++) acc[mt][nt][j] = 0.f;

    float4 av[NLA], wv[NLB];
    #pragma unroll
    for (int t = 0; t < NLA; t++) {
        int id = tid + t*THREADS, r = id >> 2, kq = id & 3;
        av[t] = *(const float4*)(A + (size_t)(bm + r)*K + kq*4);
    }
    #pragma unroll
    for (int t = 0; t < NLB; t++) {
        int id = tid + t*THREADS, r = id >> 2, kq = id & 3;
        wv[t] = *(const float4*)(W + (size_t)(bn + r)*K + kq*4);
    }

    auto stage = [&](int buf) {
        #pragma unroll
        for (int t = 0; t < NLA; t++) {
            int id = tid + t*THREADS, r = id >> 2, kq = id & 3;
            uint32_t h0, l0, h1, l1;
            bf16_split2(av[t].x, av[t].y, h0, l0);
            bf16_split2(av[t].z, av[t].w, h1, l1);
            As_hi[buf][2*kq  ][r] = h0;
            As_hi[buf][2*kq+1][r] = h1;
            As_lo[buf][2*kq  ][r] = l0;
            As_lo[buf][2*kq+1][r] = l1;
        }
        #pragma unroll
        for (int t = 0; t < NLB; t++) {
            int id = tid + t*THREADS, r = id >> 2, kq = id & 3;
            uint32_t h0, l0, h1, l1;
            bf16_split2(wv[t].x, wv[t].y, h0, l0);
            bf16_split2(wv[t].z, wv[t].w, h1, l1);
            Ws_hi[buf][2*kq  ][r] = h0;
            Ws_hi[buf][2*kq+1][r] = h1;
            Ws_lo[buf][2*kq  ][r] = l0;
            Ws_lo[buf][2*kq+1][r] = l1;
        }
    };

    stage(0);
    __syncthreads();

    const int nk = K / KT;
    for (int kt = 0; kt < nk; kt++) {
        const int buf = kt & 1;
        if (kt + 1 < nk) {
            int k0 = (kt + 1) * KT;
            #pragma unroll
            for (int t = 0; t < NLA; t++) {
                int id = tid + t*THREADS, r = id >> 2, kq = id & 3;
                av[t] = *(const float4*)(A + (size_t)(bm + r)*K + k0 + kq*4);
            }
            #pragma unroll
            for (int t = 0; t < NLB; t++) {
                int id = tid + t*THREADS, r = id >> 2, kq = id & 3;
                wv[t] = *(const float4*)(W + (size_t)(bn + r)*K + k0 + kq*4);
            }
        }

        uint32_t ah[MT][4], al[MT][4];
        #pragma unroll
        for (int mt = 0; mt < MT; mt++) {
            int m = wrow*WM + mt*16 + gr;
            ah[mt][0] = As_hi[buf][ct  ][m];
            ah[mt][1] = As_hi[buf][ct  ][m + 8];
            ah[mt][2] = As_hi[buf][ct+4][m];
            ah[mt][3] = As_hi[buf][ct+4][m + 8];
            al[mt][0] = As_lo[buf][ct  ][m];
            al[mt][1] = As_lo[buf][ct  ][m + 8];
            al[mt][2] = As_lo[buf][ct+4][m];
            al[mt][3] = As_lo[buf][ct+4][m + 8];
        }
        #pragma unroll
        for (int nt = 0; nt < NT; nt++) {
            int n = wcol*WN + nt*8 + gr;
            uint32_t bh0 = Ws_hi[buf][ct  ][n];
            uint32_t bh1 = Ws_hi[buf][ct+4][n];
            uint32_t bl0 = Ws_lo[buf][ct  ][n];
            uint32_t bl1 = Ws_lo[buf][ct+4][n];
            #pragma unroll
            for (int mt = 0; mt < MT; mt++) {
                mma_bf16(acc[mt][nt], al[mt], bh0, bh1);   // lo*hi
                mma_bf16(acc[mt][nt], ah[mt], bl0, bl1);   // hi*lo
                mma_bf16(acc[mt][nt], ah[mt], bh0, bh1);   // hi*hi
            }
        }

        if (kt + 1 < nk) stage(buf ^ 1);
        __syncthreads();
    }

    // epilogue: C-frag m16n8: c0,c1 at (gr, ct*2..+1), c2,c3 at (gr+8, same)
    #pragma unroll
    for (int mt = 0; mt < MT; mt++) {
        int row = bm + wrow*WM + mt*16 + gr;
        #pragma unroll
        for (int nt = 0; nt < NT; nt++) {
            int col = bn + wcol*WN + nt*8 + ct*2;
            float b0 = bias[col], b1 = bias[col + 1];
            float c0 = acc[mt][nt][0] + b0;
            float c1 = acc[mt][nt][1] + b1;
            float c2 = acc[mt][nt][2] + b0;
            float c3 = acc[mt][nt][3] + b1;
            if (EPI == 1) {
                c0 = gelu_exact(c0); c1 = gelu_exact(c1);
                c2 = gelu_exact(c2); c3 = gelu_exact(c3);
            }
            if (EPI == 2) {
                float2 r0 = *(const float2*)(res + (size_t)row*N + col);
                float2 r1 = *(const float2*)(res + (size_t)(row + 8)*N + col);
                c0 += r0.x; c1 += r0.y; c2 += r1.x; c3 += r1.y;
            }
            *(float2*)(C + (size_t)row*N + col)       = make_float2(c0, c1);
            *(float2*)(C + (size_t)(row + 8)*N + col) = make_float2(c2, c3);
        }
    }
}

// ---------------- attention: block = (b, head, half); 128 queries/block -----
__global__ void attention_kernel(const float* __restrict__ qkv,
                                 float* __restrict__ outp) {
    __shared__ float Ks[S_][DH_];
    int bid  = blockIdx.x;
    int half = bid & 1;
    int bh   = bid >> 1;
    int b    = bh >> 3, h = bh & 7;
    int tid  = threadIdx.x;                 // 0..127
    const float* base = qkv + (size_t)b*S_*(3*H_);
    #pragma unroll
    for (int r = tid; r < S_; r += 128) {
        const float4* kr = (const float4*)(base + (size_t)r*(3*H_) + H_ + h*DH_);
        float4* dst = (float4*)&Ks[r][0];
        #pragma unroll
        for (int i = 0; i < DH_/4; i++) dst[i] = kr[i];
    }
    int qrow = half*128 + tid;
    float q[DH_];
    {
        const float4* qr = (const float4*)(base + (size_t)qrow*(3*H_) + h*DH_);
        #pragma unroll
        for (int i = 0; i < DH_/4; i++) ((float4*)q)[i] = qr[i];
    }
    __syncthreads();

    const float scale = 0.17677669529663688110f;   // 1/sqrt(32)
    float m = -INFINITY, l = 0.f;
    float acc[DH_];
    #pragma unroll
    for (int d = 0; d < DH_; d++) acc[d] = 0.f;
    const float* vbase = base + 2*H_ + h*DH_;

    for (int j = 0; j < S_; j += 2) {
        float d0 = 0.f, d1 = 0.f, d2 = 0.f, d3 = 0.f;
        float e0 = 0.f, e1 = 0.f, e2 = 0.f, e3 = 0.f;
        #pragma unroll
        for (int i = 0; i < DH_/4; i++) {
            float4 k0 = ((const float4*)&Ks[j][0])[i];
            float4 k1 = ((const float4*)&Ks[j+1][0])[i];
            d0 = fmaf(q[4*i+0], k0.x, d0);
            d1 = fmaf(q[4*i+1], k0.y, d1);
            d2 = fmaf(q[4*i+2], k0.z, d2);
            d3 = fmaf(q[4*i+3], k0.w, d3);
            e0 = fmaf(q[4*i+0], k1.x, e0);
            e1 = fmaf(q[4*i+1], k1.y, e1);
            e2 = fmaf(q[4*i+2], k1.z, e2);
            e3 = fmaf(q[4*i+3], k1.w, e3);
        }
        float s0 = ((d0 + d1) + (d2 + d3)) * scale;
        float s1 = ((e0 + e1) + (e2 + e3)) * scale;
        float mn = fmaxf(m, fmaxf(s0, s1));
        float c  = __expf(m - mn);
        float p0 = __expf(s0 - mn);
        float p1 = __expf(s1 - mn);
        l = l*c + p0 + p1;
        const float4* v0 = (const float4*)(vbase + (size_t)j*(3*H_));
        const float4* v1 = (const float4*)(vbase + (size_t)(j+1)*(3*H_));
        #pragma unroll
        for (int i = 0; i < DH_/4; i++) {
            float4 a = v0[i], bq = v1[i];
            acc[i*4+0] = fmaf(acc[i*4+0], c, fmaf(p0, a.x, p1*bq.x));
            acc[i*4+1] = fmaf(acc[i*4+1], c, fmaf(p0, a.y, p1*bq.y));
            acc[i*4+2] = fmaf(acc[i*4+2], c, fmaf(p0, a.z, p1*bq.z));
            acc[i*4+3] = fmaf(acc[i*4+3], c, fmaf(p0, a.w, p1*bq.w));
        }
        m = mn;
    }
    float inv = 1.0f / l;
    float* orow = outp + (size_t)(b*S_ + qrow)*H_ + h*DH_;
    #pragma unroll
    for (int d = 0; d < DH_; d++) orow[d] = acc[d]*inv;
}

// ---------------- layernorm: single-pass (sum + sumsq), block per row -------
__global__ void layernorm_kernel(const float* __restrict__ in,
                                 const float* __restrict__ gw,
                                 const float* __restrict__ gb,
                                 float* __restrict__ outp) {
    __shared__ float red1[8], red2[8];
    __shared__ float s_mean, s_rstd;
    int row = blockIdx.x, tid = threadIdx.x;
    float v = in[(size_t)row*H_ + tid];
    float s1 = v, s2 = v*v;
    #pragma unroll
    for (int o = 16; o > 0; o >>= 1) {
        s1 += __shfl_xor_sync(0xffffffffu, s1, o);
        s2 += __shfl_xor_sync(0xffffffffu, s2, o);
    }
    if ((tid & 31) == 0) { red1[tid >> 5] = s1; red2[tid >> 5] = s2; }
    __syncthreads();
    if (tid == 0) {
        float t1 = 0.f, t2 = 0.f;
        #pragma unroll
        for (int i = 0; i < 8; i++) { t1 += red1[i]; t2 += red2[i]; }
        float mean = t1 * (1.0f/H_);
        float var  = t2 * (1.0f/H_) - mean*mean;
        s_mean = mean;
        s_rstd = rsqrtf(var + 1e-5f);
    }
    __syncthreads();
    outp[(size_t)row*H_ + tid] = (v - s_mean) * s_rstd * gw[tid] + gb[tid];
}

// ---------------- head2: logits (M x 13), one thread per output ----------
__global__ void head2_kernel(const float* __restrict__ X,
                             const float* __restrict__ W,
                             const float* __restrict__ bias) {
    int t = blockIdx.x * blockDim.x + threadIdx.x;
    if (t >= B_*S_*NC_) return;
    int row = t / NC_, c = t - row*NC_;
    const float4* x = (const float4*)(X + (size_t)row*H_);
    const float4* w = (const float4*)(W + (size_t)c*H_);
    float s0 = 0.f, s1 = 0.f, s2 = 0.f, s3 = 0.f;
    #pragma unroll 8
    for (int k = 0; k < H_/4; k++) {
        float4 xv = x[k], wv = w[k];
        s0 = fmaf(xv.x, wv.x, s0); s1 = fmaf(xv.y, wv.y, s1);
        s2 = fmaf(xv.z, wv.z, s2); s3 = fmaf(xv.w, wv.w, s3);
    }
    g_logits[t] = (s0+s1) + (s2+s3) + bias[c];
}

// ---------------- final gather to point logits ----------
__global__ void gather_kernel(float* __restrict__ out) {
    int t = blockIdx.x * blockDim.x + threadIdx.x;
    if (t >= B_*N_*NC_) return;
    int r = t / NC_;
    int c = t - r*NC_;
    int b = r >> 15;                // r / N_
    int a = g_assign[r];
    out[t] = g_logits[(b*S_ + a)*NC_ + c];
}

// ---------------- host launcher ----------
extern "C" void kernel_launch(void* const* d_in, const int* in_sizes, int n_in,
                              void* d_out, int out_size) {
    const float* xyz      = (const float*)d_in[0];
    const float* feat     = (const float*)d_in[1];
    const int*   seed_idx = (const int*)  d_in[2];
    const float* proj_w   = (const float*)d_in[3];
    const float* proj_b   = (const float*)d_in[4];
    const float* qkv_w    = (const float*)d_in[5];
    const float* qkv_b    = (const float*)d_in[6];
    const float* out_w    = (const float*)d_in[7];
    const float* out_b    = (const float*)d_in[8];
    const float* ln1_g    = (const float*)d_in[9];
    const float* ln1_b    = (const float*)d_in[10];
    const float* ln2_g    = (const float*)d_in[11];
    const float* ln2_b    = (const float*)d_in[12];
    const float* ff1_w    = (const float*)d_in[13];
    const float* ff1_b    = (const float*)d_in[14];
    const float* ff2_w    = (const float*)d_in[15];
    const float* ff2_b    = (const float*)d_in[16];
    const float* hln_g    = (const float*)d_in[17];
    const float* hln_b    = (const float*)d_in[18];
    const float* h1_w     = (const float*)d_in[19];
    const float* h1_b     = (const float*)d_in[20];
    const float* h2_w     = (const float*)d_in[21];
    const float* h2_b     = (const float*)d_in[22];
    float* out = (float*)d_out;

    float *p_x, *p_qkv, *p_attn, *p_tmp, *p_ff, *p_h1;
    cudaGetSymbolAddress((void**)&p_x,    g_x);
    cudaGetSymbolAddress((void**)&p_qkv,  g_qkv);
    cudaGetSymbolAddress((void**)&p_attn, g_attn);
    cudaGetSymbolAddress((void**)&p_tmp,  g_tmp);
    cudaGetSymbolAddress((void**)&p_ff,   g_ff);
    cudaGetSymbolAddress((void**)&p_h1,   g_h1);

    const int M = B_*S_;   // 4096

    zero_kernel<<<(B_*S_*4 + 255)/256, 256>>>();
    assign_kernel<<<B_*16, 256>>>(xyz, feat, seed_idx);
    tokens_kernel<<<B_*S_, 256>>>(xyz, seed_idx, proj_w, proj_b);

    for (int l = 0; l < 2; l++) {
        // QKV: M=4096, N=768, K=256 -> 64x128 tiles, grid 6x64=384, 4 CTA/SM
        sgemm_tc<64,128,64,32,128,4,0><<<dim3(3*H_/128, M/64), 128>>>(
            p_x, qkv_w + (size_t)l*3*H_*H_, qkv_b + l*3*H_, nullptr, p_qkv,
            M, 3*H_, H_);
        attention_kernel<<<B_*NH_*2, 128>>>(p_qkv, p_attn);
        // out-proj: N=256, K=256 -> 64x64 tiles, grid 4x64=256
        sgemm_tc<64,64,32,32,128,4,2><<<dim3(H_/64, M/64), 128>>>(
            p_attn, out_w + (size_t)l*H_*H_, out_b + l*H_, p_x, p_tmp,
            M, H_, H_);
        layernorm_kernel<<<M, 256>>>(p_tmp, ln1_g + l*H_, ln1_b + l*H_, p_x);
        // FF1: N=1024, K=256 -> 64x128 tiles, grid 8x64=512, 4 CTA/SM
        sgemm_tc<64,128,64,32,128,4,1><<<dim3(DFF_/128, M/64), 128>>>(
            p_x, ff1_w + (size_t)l*DFF_*H_, ff1_b + l*DFF_, nullptr, p_ff,
            M, DFF_, H_);
        // FF2: N=256, K=1024 -> 64x64 tiles
        sgemm_tc<64,64,32,32,128,4,2><<<dim3(H_/64, M/64), 128>>>(
            p_ff, ff2_w + (size_t)l*H_*DFF_, ff2_b + l*H_, p_x, p_tmp,
            M, H_, DFF_);
        layernorm_kernel<<<M, 256>>>(p_tmp, ln2_g + l*H_, ln2_b + l*H_, p_x);
    }

    layernorm_kernel<<<M, 256>>>(p_x, hln_g, hln_b, p_tmp);
    sgemm_tc<64,64,32,32,128,4,1><<<dim3(H_/64, M/64), 128>>>(
        p_tmp, h1_w, h1_b, nullptr, p_h1, M, H_, H_);
    head2_kernel<<<(M*NC_ + 255)/256, 256>>>(p_h1, h2_w, h2_b);
    gather_kernel<<<(B_*N_*NC_ + 255)/256, 256>>>(out);
}

// round 11
// speedup vs baseline: 1.2909x; 1.0129x over previous
#include <cuda_runtime.h>
#include <cuda_bf16.h>
#include <math.h>
#include <stdint.h>

#define B_   16
#define N_   32768
#define S_   256
#define H_   256
#define NH_  8
#define DH_  32
#define DFF_ 1024
#define NC_  13

// pre-split transposed weight pool offsets (uint32 elements)
#define OFF_QKV 0
#define OFF_OUT 196608
#define OFF_FF1 262144
#define OFF_FF2 524288
#define OFF_H1  786432
#define W_TOTAL 819200

// ---------------- scratch (device globals; no allocations allowed) ----------
__device__ float g_sumxyz[B_*S_*3];
__device__ float g_sumfeat[B_*S_*4];
__device__ float g_cnt[B_*S_];
__device__ int   g_assign[B_*N_];
__device__ float g_x[B_*S_*H_];
__device__ float g_qkv[B_*S_*3*H_];
__device__ float g_attn[B_*S_*H_];
__device__ float g_tmp[B_*S_*H_];
__device__ float g_ff[B_*S_*DFF_];
__device__ float g_h1[B_*S_*H_];
__device__ float g_logits[B_*S_*NC_];
__device__ uint32_t g_Whi[W_TOTAL];
__device__ uint32_t g_Wlo[W_TOTAL];

// ---------------- utils ----------
__device__ __forceinline__ float gelu_exact(float x) {
    return 0.5f * x * (1.0f + erff(x * 0.70710678118654752440f));
}

// split a float2 into packed bf16x2 hi and lo: x = hi + lo + O(2^-18 x)
__device__ __forceinline__ void bf16_split2(float fx, float fy,
                                            uint32_t& hi, uint32_t& lo) {
    __nv_bfloat162 h = __float22bfloat162_rn(make_float2(fx, fy));
    hi = *(uint32_t*)&h;
    float2 hf = __bfloat1622float2(h);
    __nv_bfloat162 l = __float22bfloat162_rn(make_float2(fx - hf.x, fy - hf.y));
    lo = *(uint32_t*)&l;
}

__device__ __forceinline__ void mma_bf16(float* d, const uint32_t* a,
                                         uint32_t b0, uint32_t b1) {
    asm volatile(
        "mma.sync.aligned.m16n8k16.row.col.f32.bf16.bf16.f32 "
        "{%0,%1,%2,%3},{%4,%5,%6,%7},{%8,%9},{%0,%1,%2,%3};"
        : "+f"(d[0]), "+f"(d[1]), "+f"(d[2]), "+f"(d[3])
        : "r"(a[0]), "r"(a[1]), "r"(a[2]), "r"(a[3]), "r"(b0), "r"(b1));
}

// ---------------- weight split + transpose: W[N][K] -> hi/lo [K/2][N] ------
// dst[l][kp][n] = bf16_split(W[l][n][2kp], W[l][n][2kp+1])
__global__ void split_t_kernel(const float* __restrict__ src,
                               uint32_t* __restrict__ hi,
                               uint32_t* __restrict__ lo,
                               int Nw, int Kp, int total,
                               int lstrideS, int lstrideD) {
    int id = blockIdx.x * blockDim.x + threadIdx.x;
    if (id >= total) return;
    int l   = id / (Kp * Nw);
    int rem = id - l * (Kp * Nw);
    int n   = rem / Kp;
    int kp  = rem - n * Kp;
    const float* s = src + (size_t)l*lstrideS + (size_t)n*(2*Kp) + 2*kp;
    uint32_t h, lw;
    bf16_split2(s[0], s[1], h, lw);
    size_t d = (size_t)l*lstrideD + (size_t)kp*Nw + n;
    hi[d] = h;
    lo[d] = lw;
}

// ---------------- zero the segment accumulators ----------
__global__ void zero_kernel() {
    int t = blockIdx.x * blockDim.x + threadIdx.x;
    if (t < B_*S_*3) g_sumxyz[t]  = 0.f;
    if (t < B_*S_*4) g_sumfeat[t] = 0.f;
    if (t < B_*S_)   g_cnt[t]     = 0.f;
}

// ---------------- point -> seed argmin + block-local segment sums ----------
__global__ void assign_kernel(const float* __restrict__ xyz,
                              const float* __restrict__ feat,
                              const int*   __restrict__ seed_idx) {
    __shared__ float4 s_seed[S_];
    __shared__ float s_acc[S_*8];
    int b     = blockIdx.x >> 4;
    int chunk = blockIdx.x & 15;
    int tid   = threadIdx.x;

    {
        int idx = seed_idx[tid];
        float a0 = xyz[(size_t)(b*N_ + idx)*3 + 0];
        float a1 = xyz[(size_t)(b*N_ + idx)*3 + 1];
        float a2 = xyz[(size_t)(b*N_ + idx)*3 + 2];
        s_seed[tid] = make_float4(a0, a1, a2, (a0*a0 + a1*a1) + a2*a2);
    }
    #pragma unroll
    for (int i = 0; i < 8; i++) s_acc[tid + i*256] = 0.f;
    __syncthreads();

    for (int pp = 0; pp < 2; pp++) {
        int n0 = chunk*2048 + pp*1024;
        float px[4], py[4], pz[4], pw[4];
        #pragma unroll
        for (int i = 0; i < 4; i++) {
            size_t off = (size_t)(b*N_ + n0 + i*256 + tid);
            px[i] = xyz[off*3+0];
            py[i] = xyz[off*3+1];
            pz[i] = xyz[off*3+2];
            pw[i] = (px[i]*px[i] + py[i]*py[i]) + pz[i]*pz[i];
        }
        float best[4] = {INFINITY, INFINITY, INFINITY, INFINITY};
        int   bi[4]   = {0, 0, 0, 0};
        #pragma unroll 2
        for (int s = 0; s < S_; s++) {
            float4 sd = s_seed[s];
            #pragma unroll
            for (int i = 0; i < 4; i++) {
                float d = px[i] * sd.x;
                d = fmaf(py[i], sd.y, d);
                d = fmaf(pz[i], sd.z, d);
                float d2 = (pw[i] + sd.w) - 2.0f*d;
                if (d2 < best[i]) { best[i] = d2; bi[i] = s; }  // first wins
            }
        }
        #pragma unroll
        for (int i = 0; i < 4; i++) {
            size_t off = (size_t)(b*N_ + n0 + i*256 + tid);
            g_assign[off] = bi[i];
            float4 f = ((const float4*)feat)[off];
            float* a = &s_acc[bi[i]*8];
            atomicAdd(a+0, px[i]); atomicAdd(a+1, py[i]); atomicAdd(a+2, pz[i]);
            atomicAdd(a+3, f.x);   atomicAdd(a+4, f.y);
            atomicAdd(a+5, f.z);   atomicAdd(a+6, f.w);
            atomicAdd(a+7, 1.0f);
        }
    }
    __syncthreads();

    int s  = tid;
    int bs = b*S_ + s;
    atomicAdd(&g_sumxyz [bs*3+0], s_acc[s*8+0]);
    atomicAdd(&g_sumxyz [bs*3+1], s_acc[s*8+1]);
    atomicAdd(&g_sumxyz [bs*3+2], s_acc[s*8+2]);
    atomicAdd(&g_sumfeat[bs*4+0], s_acc[s*8+3]);
    atomicAdd(&g_sumfeat[bs*4+1], s_acc[s*8+4]);
    atomicAdd(&g_sumfeat[bs*4+2], s_acc[s*8+5]);
    atomicAdd(&g_sumfeat[bs*4+3], s_acc[s*8+6]);
    atomicAdd(&g_cnt[bs],         s_acc[s*8+7]);
}

// ---------------- superpoint features -> token projection ----------
__global__ void tokens_kernel(const float* __restrict__ xyz,
                              const int*   __restrict__ seed_idx,
                              const float* __restrict__ pw,
                              const float* __restrict__ pb) {
    __shared__ float sp[7];
    int bs  = blockIdx.x;
    int b   = bs >> 8, s = bs & 255;
    int tid = threadIdx.x;
    if (tid == 0) {
        float cnt   = g_cnt[bs];
        float denom = fmaxf(cnt, 1.0f);
        bool  empty = (cnt == 0.0f);
        int   idx   = seed_idx[s];
        #pragma unroll
        for (int c = 0; c < 3; c++) {
            float seedc = xyz[(size_t)(b*N_ + idx)*3 + c];
            sp[c] = empty ? seedc : g_sumxyz[bs*3+c] / denom;
        }
        #pragma unroll
        for (int c = 0; c < 4; c++)
            sp[3+c] = empty ? 0.f : g_sumfeat[bs*4+c] / denom;
    }
    __syncthreads();
    float acc = 0.f;
    #pragma unroll
    for (int i = 0; i < 7; i++) acc = fmaf(sp[i], pw[tid*7 + i], acc);
    g_x[(size_t)bs*H_ + tid] = acc + pb[tid];
}

// ---------------- tensor-core GEMM (3xBF16, m16n8k16): C = epi(A@Wt + b) ---
// A: fp32, split in-kernel. W: PRE-SPLIT transposed bf16 hi/lo [K/2][Nw]
// (staging is a straight LDG.128 -> STS.128 copy). 3 passes:
// al*bh + ah*bl + ah*bh (dropped lo*lo ~2^-18).
// KT=16, double-buffered, +8 pad => conflict-free fragment LDS.
// EPI: 0 = none, 1 = gelu, 2 = +residual
template<int TM, int TN, int WM, int WN, int THREADS, int MINCTA, int EPI>
__global__ void __launch_bounds__(THREADS, MINCTA)
sgemm_tc(const float* __restrict__ A,
         const uint32_t* __restrict__ Whi, const uint32_t* __restrict__ Wlo,
         const float* __restrict__ bias, const float* __restrict__ res,
         float* __restrict__ C, int M, int N, int K, int Nw) {
    constexpr int KT = 16;
    constexpr int PA = TM + 8;
    constexpr int PB = TN + 8;
    constexpr int WCOLS = TN / WN;
    constexpr int MT = WM / 16;
    constexpr int NT = WN / 8;
    constexpr int NLA = TM * 4 / THREADS;   // A float4 loads per thread
    constexpr int WU  = TN * 2 / THREADS;   // W uint4 loads per thread per array
    constexpr int C4  = TN / 4;             // uint4 per kpair row

    __shared__ __align__(16) uint32_t As_hi[2][8][PA];
    __shared__ __align__(16) uint32_t As_lo[2][8][PA];
    __shared__ __align__(16) uint32_t Ws_hi[2][8][PB];
    __shared__ __align__(16) uint32_t Ws_lo[2][8][PB];

    const int tid  = threadIdx.x;
    const int lane = tid & 31;
    const int wid  = tid >> 5;
    const int wrow = wid / WCOLS;
    const int wcol = wid % WCOLS;
    const int gr   = lane >> 2;          // 0..7
    const int ct   = lane & 3;           // 0..3
    const int bm   = blockIdx.y * TM;
    const int bn   = blockIdx.x * TN;

    float acc[MT][NT][4];
    #pragma unroll
    for (int mt = 0; mt < MT; mt++)
        #pragma unroll
        for (int nt = 0; nt < NT; nt++)
            #pragma unroll
            for (int j = 0; j < 4; j++) acc[mt][nt][j] = 0.f;

    float4 av[NLA];
    uint4  wh[WU], wl[WU];

    #pragma unroll
    for (int t = 0; t < NLA; t++) {
        int id = tid + t*THREADS, r = id >> 2, kq = id & 3;
        av[t] = *(const float4*)(A + (size_t)(bm + r)*K + kq*4);
    }
    #pragma unroll
    for (int t = 0; t < WU; t++) {
        int u = tid + t*THREADS, kp = u / C4, c4 = u % C4;
        size_t base = (size_t)kp*Nw + bn + c4*4;
        wh[t] = *(const uint4*)(Whi + base);
        wl[t] = *(const uint4*)(Wlo + base);
    }

    auto stage = [&](int buf) {
        #pragma unroll
        for (int t = 0; t < NLA; t++) {
            int id = tid + t*THREADS, r = id >> 2, kq = id & 3;
            uint32_t h0, l0, h1, l1;
            bf16_split2(av[t].x, av[t].y, h0, l0);
            bf16_split2(av[t].z, av[t].w, h1, l1);
            As_hi[buf][2*kq  ][r] = h0;
            As_hi[buf][2*kq+1][r] = h1;
            As_lo[buf][2*kq  ][r] = l0;
            As_lo[buf][2*kq+1][r] = l1;
        }
        #pragma unroll
        for (int t = 0; t < WU; t++) {
            int u = tid + t*THREADS, kp = u / C4, c4 = u % C4;
            *(uint4*)&Ws_hi[buf][kp][c4*4] = wh[t];
            *(uint4*)&Ws_lo[buf][kp][c4*4] = wl[t];
        }
    };

    stage(0);
    __syncthreads();

    const int nk = K / KT;
    for (int kt = 0; kt < nk; kt++) {
        const int buf = kt & 1;
        if (kt + 1 < nk) {
            int k0 = (kt + 1) * KT;
            #pragma unroll
            for (int t = 0; t < NLA; t++) {
                int id = tid + t*THREADS, r = id >> 2, kq = id & 3;
                av[t] = *(const float4*)(A + (size_t)(bm + r)*K + k0 + kq*4);
            }
            int kp0 = (kt + 1) * 8;
            #pragma unroll
            for (int t = 0; t < WU; t++) {
                int u = tid + t*THREADS, kp = u / C4, c4 = u % C4;
                size_t base = (size_t)(kp0 + kp)*Nw + bn + c4*4;
                wh[t] = *(const uint4*)(Whi + base);
                wl[t] = *(const uint4*)(Wlo + base);
            }
        }

        uint32_t ah[MT][4], al[MT][4];
        #pragma unroll
        for (int mt = 0; mt < MT; mt++) {
            int m = wrow*WM + mt*16 + gr;
            ah[mt][0] = As_hi[buf][ct  ][m];
            ah[mt][1] = As_hi[buf][ct  ][m + 8];
            ah[mt][2] = As_hi[buf][ct+4][m];
            ah[mt][3] = As_hi[buf][ct+4][m + 8];
            al[mt][0] = As_lo[buf][ct  ][m];
            al[mt][1] = As_lo[buf][ct  ][m + 8];
            al[mt][2] = As_lo[buf][ct+4][m];
            al[mt][3] = As_lo[buf][ct+4][m + 8];
        }
        #pragma unroll
        for (int nt = 0; nt < NT; nt++) {
            int n = wcol*WN + nt*8 + gr;
            uint32_t bh0 = Ws_hi[buf][ct  ][n];
            uint32_t bh1 = Ws_hi[buf][ct+4][n];
            uint32_t bl0 = Ws_lo[buf][ct  ][n];
            uint32_t bl1 = Ws_lo[buf][ct+4][n];
            #pragma unroll
            for (int mt = 0; mt < MT; mt++) {
                mma_bf16(acc[mt][nt], al[mt], bh0, bh1);   // lo*hi
                mma_bf16(acc[mt][nt], ah[mt], bl0, bl1);   // hi*lo
                mma_bf16(acc[mt][nt], ah[mt], bh0, bh1);   // hi*hi
            }
        }

        if (kt + 1 < nk) stage(buf ^ 1);
        __syncthreads();
    }

    // epilogue: C-frag m16n8: c0,c1 at (gr, ct*2..+1), c2,c3 at (gr+8, same)
    #pragma unroll
    for (int mt = 0; mt < MT; mt++) {
        int row = bm + wrow*WM + mt*16 + gr;
        #pragma unroll
        for (int nt = 0; nt < NT; nt++) {
            int col = bn + wcol*WN + nt*8 + ct*2;
            float b0 = bias[col], b1 = bias[col + 1];
            float c0 = acc[mt][nt][0] + b0;
            float c1 = acc[mt][nt][1] + b1;
            float c2 = acc[mt][nt][2] + b0;
            float c3 = acc[mt][nt][3] + b1;
            if (EPI == 1) {
                c0 = gelu_exact(c0); c1 = gelu_exact(c1);
                c2 = gelu_exact(c2); c3 = gelu_exact(c3);
            }
            if (EPI == 2) {
                float2 r0 = *(const float2*)(res + (size_t)row*N + col);
                float2 r1 = *(const float2*)(res + (size_t)(row + 8)*N + col);
                c0 += r0.x; c1 += r0.y; c2 += r1.x; c3 += r1.y;
            }
            *(float2*)(C + (size_t)row*N + col)       = make_float2(c0, c1);
            *(float2*)(C + (size_t)(row + 8)*N + col) = make_float2(c2, c3);
        }
    }
}

// ---------------- attention: block = (b, head, half); 128 queries/block -----
__global__ void attention_kernel(const float* __restrict__ qkv,
                                 float* __restrict__ outp) {
    __shared__ float Ks[S_][DH_];
    int bid  = blockIdx.x;
    int half = bid & 1;
    int bh   = bid >> 1;
    int b    = bh >> 3, h = bh & 7;
    int tid  = threadIdx.x;                 // 0..127
    const float* base = qkv + (size_t)b*S_*(3*H_);
    #pragma unroll
    for (int r = tid; r < S_; r += 128) {
        const float4* kr = (const float4*)(base + (size_t)r*(3*H_) + H_ + h*DH_);
        float4* dst = (float4*)&Ks[r][0];
        #pragma unroll
        for (int i = 0; i < DH_/4; i++) dst[i] = kr[i];
    }
    int qrow = half*128 + tid;
    float q[DH_];
    {
        const float4* qr = (const float4*)(base + (size_t)qrow*(3*H_) + h*DH_);
        #pragma unroll
        for (int i = 0; i < DH_/4; i++) ((float4*)q)[i] = qr[i];
    }
    __syncthreads();

    const float scale = 0.17677669529663688110f;   // 1/sqrt(32)
    float m = -INFINITY, l = 0.f;
    float acc[DH_];
    #pragma unroll
    for (int d = 0; d < DH_; d++) acc[d] = 0.f;
    const float* vbase = base + 2*H_ + h*DH_;

    for (int j = 0; j < S_; j += 2) {
        float d0 = 0.f, d1 = 0.f, d2 = 0.f, d3 = 0.f;
        float e0 = 0.f, e1 = 0.f, e2 = 0.f, e3 = 0.f;
        #pragma unroll
        for (int i = 0; i < DH_/4; i++) {
            float4 k0 = ((const float4*)&Ks[j][0])[i];
            float4 k1 = ((const float4*)&Ks[j+1][0])[i];
            d0 = fmaf(q[4*i+0], k0.x, d0);
            d1 = fmaf(q[4*i+1], k0.y, d1);
            d2 = fmaf(q[4*i+2], k0.z, d2);
            d3 = fmaf(q[4*i+3], k0.w, d3);
            e0 = fmaf(q[4*i+0], k1.x, e0);
            e1 = fmaf(q[4*i+1], k1.y, e1);
            e2 = fmaf(q[4*i+2], k1.z, e2);
            e3 = fmaf(q[4*i+3], k1.w, e3);
        }
        float s0 = ((d0 + d1) + (d2 + d3)) * scale;
        float s1 = ((e0 + e1) + (e2 + e3)) * scale;
        float mn = fmaxf(m, fmaxf(s0, s1));
        float c  = __expf(m - mn);
        float p0 = __expf(s0 - mn);
        float p1 = __expf(s1 - mn);
        l = l*c + p0 + p1;
        const float4* v0 = (const float4*)(vbase + (size_t)j*(3*H_));
        const float4* v1 = (const float4*)(vbase + (size_t)(j+1)*(3*H_));
        #pragma unroll
        for (int i = 0; i < DH_/4; i++) {
            float4 a = v0[i], bq = v1[i];
            acc[i*4+0] = fmaf(acc[i*4+0], c, fmaf(p0, a.x, p1*bq.x));
            acc[i*4+1] = fmaf(acc[i*4+1], c, fmaf(p0, a.y, p1*bq.y));
            acc[i*4+2] = fmaf(acc[i*4+2], c, fmaf(p0, a.z, p1*bq.z));
            acc[i*4+3] = fmaf(acc[i*4+3], c, fmaf(p0, a.w, p1*bq.w));
        }
        m = mn;
    }
    float inv = 1.0f / l;
    float* orow = outp + (size_t)(b*S_ + qrow)*H_ + h*DH_;
    #pragma unroll
    for (int d = 0; d < DH_; d++) orow[d] = acc[d]*inv;
}

// ---------------- layernorm: warp-per-row, barrier-free ----------
// block = 256 thr = 8 warps = 8 rows; lane holds 8 consecutive values.
__global__ void layernorm_kernel(const float* __restrict__ in,
                                 const float* __restrict__ gw,
                                 const float* __restrict__ gb,
                                 float* __restrict__ outp) {
    int warp = threadIdx.x >> 5;
    int lane = threadIdx.x & 31;
    int row  = blockIdx.x * 8 + warp;
    const float4* in4 = (const float4*)in;
    float4 a = in4[(size_t)row*64 + lane*2];
    float4 b = in4[(size_t)row*64 + lane*2 + 1];
    float s1 = ((a.x + a.y) + (a.z + a.w)) + ((b.x + b.y) + (b.z + b.w));
    float s2 = ((a.x*a.x + a.y*a.y) + (a.z*a.z + a.w*a.w))
             + ((b.x*b.x + b.y*b.y) + (b.z*b.z + b.w*b.w));
    #pragma unroll
    for (int o = 16; o > 0; o >>= 1) {
        s1 += __shfl_xor_sync(0xffffffffu, s1, o);
        s2 += __shfl_xor_sync(0xffffffffu, s2, o);
    }
    float mean = s1 * (1.0f/H_);
    float var  = s2 * (1.0f/H_) - mean*mean;
    float rstd = rsqrtf(var + 1e-5f);
    float4 g0 = ((const float4*)gw)[lane*2];
    float4 g1 = ((const float4*)gw)[lane*2 + 1];
    float4 o0 = ((const float4*)gb)[lane*2];
    float4 o1 = ((const float4*)gb)[lane*2 + 1];
    float4 r0, r1;
    r0.x = (a.x - mean)*rstd*g0.x + o0.x;
    r0.y = (a.y - mean)*rstd*g0.y + o0.y;
    r0.z = (a.z - mean)*rstd*g0.z + o0.z;
    r0.w = (a.w - mean)*rstd*g0.w + o0.w;
    r1.x = (b.x - mean)*rstd*g1.x + o1.x;
    r1.y = (b.y - mean)*rstd*g1.y + o1.y;
    r1.z = (b.z - mean)*rstd*g1.z + o1.z;
    r1.w = (b.w - mean)*rstd*g1.w + o1.w;
    ((float4*)outp)[(size_t)row*64 + lane*2]     = r0;
    ((float4*)outp)[(size_t)row*64 + lane*2 + 1] = r1;
}

// ---------------- head2: logits (M x 13), one thread per output ----------
__global__ void head2_kernel(const float* __restrict__ X,
                             const float* __restrict__ W,
                             const float* __restrict__ bias) {
    int t = blockIdx.x * blockDim.x + threadIdx.x;
    if (t >= B_*S_*NC_) return;
    int row = t / NC_, c = t - row*NC_;
    const float4* x = (const float4*)(X + (size_t)row*H_);
    const float4* w = (const float4*)(W + (size_t)c*H_);
    float s0 = 0.f, s1 = 0.f, s2 = 0.f, s3 = 0.f;
    #pragma unroll 8
    for (int k = 0; k < H_/4; k++) {
        float4 xv = x[k], wv = w[k];
        s0 = fmaf(xv.x, wv.x, s0); s1 = fmaf(xv.y, wv.y, s1);
        s2 = fmaf(xv.z, wv.z, s2); s3 = fmaf(xv.w, wv.w, s3);
    }
    g_logits[t] = (s0+s1) + (s2+s3) + bias[c];
}

// ---------------- final gather to point logits ----------
__global__ void gather_kernel(float* __restrict__ out) {
    int t = blockIdx.x * blockDim.x + threadIdx.x;
    if (t >= B_*N_*NC_) return;
    int r = t / NC_;
    int c = t - r*NC_;
    int b = r >> 15;                // r / N_
    int a = g_assign[r];
    out[t] = g_logits[(b*S_ + a)*NC_ + c];
}

// ---------------- host launcher ----------
extern "C" void kernel_launch(void* const* d_in, const int* in_sizes, int n_in,
                              void* d_out, int out_size) {
    const float* xyz      = (const float*)d_in[0];
    const float* feat     = (const float*)d_in[1];
    const int*   seed_idx = (const int*)  d_in[2];
    const float* proj_w   = (const float*)d_in[3];
    const float* proj_b   = (const float*)d_in[4];
    const float* qkv_w    = (const float*)d_in[5];
    const float* qkv_b    = (const float*)d_in[6];
    const float* out_w    = (const float*)d_in[7];
    const float* out_b    = (const float*)d_in[8];
    const float* ln1_g    = (const float*)d_in[9];
    const float* ln1_b    = (const float*)d_in[10];
    const float* ln2_g    = (const float*)d_in[11];
    const float* ln2_b    = (const float*)d_in[12];
    const float* ff1_w    = (const float*)d_in[13];
    const float* ff1_b    = (const float*)d_in[14];
    const float* ff2_w    = (const float*)d_in[15];
    const float* ff2_b    = (const float*)d_in[16];
    const float* hln_g    = (const float*)d_in[17];
    const float* hln_b    = (const float*)d_in[18];
    const float* h1_w     = (const float*)d_in[19];
    const float* h1_b     = (const float*)d_in[20];
    const float* h2_w     = (const float*)d_in[21];
    const float* h2_b     = (const float*)d_in[22];
    float* out = (float*)d_out;

    float *p_x, *p_qkv, *p_attn, *p_tmp, *p_ff, *p_h1;
    uint32_t *p_Whi, *p_Wlo;
    cudaGetSymbolAddress((void**)&p_x,    g_x);
    cudaGetSymbolAddress((void**)&p_qkv,  g_qkv);
    cudaGetSymbolAddress((void**)&p_attn, g_attn);
    cudaGetSymbolAddress((void**)&p_tmp,  g_tmp);
    cudaGetSymbolAddress((void**)&p_ff,   g_ff);
    cudaGetSymbolAddress((void**)&p_h1,   g_h1);
    cudaGetSymbolAddress((void**)&p_Whi,  g_Whi);
    cudaGetSymbolAddress((void**)&p_Wlo,  g_Wlo);

    const int M = B_*S_;   // 4096

    // one-time weight split + transpose (amortized across all GEMM K-loops)
    split_t_kernel<<<768, 256>>>(qkv_w, p_Whi+OFF_QKV, p_Wlo+OFF_QKV,
                                 768, 128, 196608, 768*256, 98304);
    split_t_kernel<<<256, 256>>>(out_w, p_Whi+OFF_OUT, p_Wlo+OFF_OUT,
                                 256, 128, 65536, 256*256, 32768);
    split_t_kernel<<<1024, 256>>>(ff1_w, p_Whi+OFF_FF1, p_Wlo+OFF_FF1,
                                 1024, 128, 262144, 1024*256, 131072);
    split_t_kernel<<<1024, 256>>>(ff2_w, p_Whi+OFF_FF2, p_Wlo+OFF_FF2,
                                 256, 512, 262144, 256*1024, 131072);
    split_t_kernel<<<128, 256>>>(h1_w, p_Whi+OFF_H1, p_Wlo+OFF_H1,
                                 256, 128, 32768, 0, 0);

    zero_kernel<<<(B_*S_*4 + 255)/256, 256>>>();
    assign_kernel<<<B_*16, 256>>>(xyz, feat, seed_idx);
    tokens_kernel<<<B_*S_, 256>>>(xyz, seed_idx, proj_w, proj_b);

    for (int l = 0; l < 2; l++) {
        // QKV: M=4096, N=768, K=256 -> 64x128 tiles, grid 6x64=384
        sgemm_tc<64,128,64,32,128,4,0><<<dim3(3*H_/128, M/64), 128>>>(
            p_x, p_Whi+OFF_QKV + l*98304, p_Wlo+OFF_QKV + l*98304,
            qkv_b + l*3*H_, nullptr, p_qkv, M, 3*H_, H_, 768);
        attention_kernel<<<B_*NH_*2, 128>>>(p_qkv, p_attn);
        // out-proj: N=256, K=256 -> 64x64 tiles, grid 4x64=256, +residual
        sgemm_tc<64,64,32,32,128,4,2><<<dim3(H_/64, M/64), 128>>>(
            p_attn, p_Whi+OFF_OUT + l*32768, p_Wlo+OFF_OUT + l*32768,
            out_b + l*H_, p_x, p_tmp, M, H_, H_, 256);
        layernorm_kernel<<<M/8, 256>>>(p_tmp, ln1_g + l*H_, ln1_b + l*H_, p_x);
        // FF1: N=1024, K=256 -> 64x128 tiles, grid 8x64=512, gelu
        sgemm_tc<64,128,64,32,128,4,1><<<dim3(DFF_/128, M/64), 128>>>(
            p_x, p_Whi+OFF_FF1 + l*131072, p_Wlo+OFF_FF1 + l*131072,
            ff1_b + l*DFF_, nullptr, p_ff, M, DFF_, H_, 1024);
        // FF2: N=256, K=1024 -> 64x64 tiles, +residual
        sgemm_tc<64,64,32,32,128,4,2><<<dim3(H_/64, M/64), 128>>>(
            p_ff, p_Whi+OFF_FF2 + l*131072, p_Wlo+OFF_FF2 + l*131072,
            ff2_b + l*H_, p_x, p_tmp, M, H_, DFF_, 256);
        layernorm_kernel<<<M/8, 256>>>(p_tmp, ln2_g + l*H_, ln2_b + l*H_, p_x);
    }

    layernorm_kernel<<<M/8, 256>>>(p_x, hln_g, hln_b, p_tmp);
    sgemm_tc<64,64,32,32,128,4,1><<<dim3(H_/64, M/64), 128>>>(
        p_tmp, p_Whi+OFF_H1, p_Wlo+OFF_H1, h1_b, nullptr, p_h1,
        M, H_, H_, 256);
    head2_kernel<<<(M*NC_ + 255)/256, 256>>>(p_h1, h2_w, h2_b);
    gather_kernel<<<(B_*N_*NC_ + 255)/256, 256>>>(out);
}

// round 12
// speedup vs baseline: 1.3847x; 1.0726x over previous
#include <cuda_runtime.h>
#include <cuda_bf16.h>
#include <math.h>
#include <stdint.h>

#define B_   16
#define N_   32768
#define S_   256
#define H_   256
#define NH_  8
#define DH_  32
#define DFF_ 1024
#define NC_  13

// pre-split transposed weight pool offsets (uint32 elements)
#define OFF_QKV 0
#define OFF_OUT 196608
#define OFF_FF1 262144
#define OFF_FF2 524288
#define OFF_H1  786432
#define W_TOTAL 819200

// ---------------- scratch (device globals; no allocations allowed) ----------
__device__ float g_sumxyz[B_*S_*3];
__device__ float g_sumfeat[B_*S_*4];
__device__ float g_cnt[B_*S_];
__device__ int   g_assign[B_*N_];
__device__ float g_x[B_*S_*H_];
__device__ float g_qkv[B_*S_*3*H_];
__device__ float g_attn[B_*S_*H_];
__device__ float g_tmp[B_*S_*H_];
__device__ float g_ff[B_*S_*DFF_];
__device__ float g_h1[B_*S_*H_];
__device__ float g_logits[B_*S_*NC_];
__device__ uint32_t g_Whi[W_TOTAL];
__device__ uint32_t g_Wlo[W_TOTAL];

// ---------------- utils ----------
__device__ __forceinline__ float gelu_exact(float x) {
    return 0.5f * x * (1.0f + erff(x * 0.70710678118654752440f));
}

// split a float2 into packed bf16x2 hi and lo: x = hi + lo + O(2^-18 x)
__device__ __forceinline__ void bf16_split2(float fx, float fy,
                                            uint32_t& hi, uint32_t& lo) {
    __nv_bfloat162 h = __float22bfloat162_rn(make_float2(fx, fy));
    hi = *(uint32_t*)&h;
    float2 hf = __bfloat1622float2(h);
    __nv_bfloat162 l = __float22bfloat162_rn(make_float2(fx - hf.x, fy - hf.y));
    lo = *(uint32_t*)&l;
}

__device__ __forceinline__ void mma_bf16(float* d, const uint32_t* a,
                                         uint32_t b0, uint32_t b1) {
    asm volatile(
        "mma.sync.aligned.m16n8k16.row.col.f32.bf16.bf16.f32 "
        "{%0,%1,%2,%3},{%4,%5,%6,%7},{%8,%9},{%0,%1,%2,%3};"
        : "+f"(d[0]), "+f"(d[1]), "+f"(d[2]), "+f"(d[3])
        : "r"(a[0]), "r"(a[1]), "r"(a[2]), "r"(a[3]), "r"(b0), "r"(b1));
}

// ---------------- merged weight split + transpose (one launch) -------------
// W[N][K] -> hi/lo [K/2][N] per layer, 5 regions dispatched by global id.
__global__ void split_all_kernel(const float* __restrict__ qkv_w,
                                 const float* __restrict__ out_w,
                                 const float* __restrict__ ff1_w,
                                 const float* __restrict__ ff2_w,
                                 const float* __restrict__ h1_w) {
    int id = blockIdx.x * blockDim.x + threadIdx.x;
    if (id >= W_TOTAL) return;
    const float* src; int Nw, Kp, off, lsS, lsD, rel;
    if (id < 262144) {
        if (id < 196608) { src=qkv_w; Nw=768;  Kp=128; off=OFF_QKV; lsS=196608; lsD=98304;  rel=id; }
        else             { src=out_w; Nw=256;  Kp=128; off=OFF_OUT; lsS=65536;  lsD=32768;  rel=id-196608; }
    } else if (id < 524288) {
        src=ff1_w; Nw=1024; Kp=128; off=OFF_FF1; lsS=262144; lsD=131072; rel=id-262144;
    } else if (id < 786432) {
        src=ff2_w; Nw=256;  Kp=512; off=OFF_FF2; lsS=262144; lsD=131072; rel=id-524288;
    } else {
        src=h1_w;  Nw=256;  Kp=128; off=OFF_H1;  lsS=0;      lsD=0;      rel=id-786432;
    }
    int l   = rel / (Kp * Nw);
    int r2  = rel - l * (Kp * Nw);
    int n   = r2 / Kp;
    int kp  = r2 - n * Kp;
    const float* s = src + (size_t)l*lsS + (size_t)n*(2*Kp) + 2*kp;
    uint32_t h, lw;
    bf16_split2(s[0], s[1], h, lw);
    size_t d = (size_t)off + (size_t)l*lsD + (size_t)kp*Nw + n;
    g_Whi[d] = h;
    g_Wlo[d] = lw;
}

// ---------------- zero the segment accumulators ----------
__global__ void zero_kernel() {
    int t = blockIdx.x * blockDim.x + threadIdx.x;
    if (t < B_*S_*3) g_sumxyz[t]  = 0.f;
    if (t < B_*S_*4) g_sumfeat[t] = 0.f;
    if (t < B_*S_)   g_cnt[t]     = 0.f;
}

// ---------------- point -> seed argmin + block-local segment sums ----------
__global__ void assign_kernel(const float* __restrict__ xyz,
                              const float* __restrict__ feat,
                              const int*   __restrict__ seed_idx) {
    __shared__ float4 s_seed[S_];
    __shared__ float s_acc[S_*8];
    int b     = blockIdx.x >> 4;
    int chunk = blockIdx.x & 15;
    int tid   = threadIdx.x;

    {
        int idx = seed_idx[tid];
        float a0 = xyz[(size_t)(b*N_ + idx)*3 + 0];
        float a1 = xyz[(size_t)(b*N_ + idx)*3 + 1];
        float a2 = xyz[(size_t)(b*N_ + idx)*3 + 2];
        s_seed[tid] = make_float4(a0, a1, a2, (a0*a0 + a1*a1) + a2*a2);
    }
    #pragma unroll
    for (int i = 0; i < 8; i++) s_acc[tid + i*256] = 0.f;
    __syncthreads();

    for (int pp = 0; pp < 2; pp++) {
        int n0 = chunk*2048 + pp*1024;
        float px[4], py[4], pz[4], pw[4];
        #pragma unroll
        for (int i = 0; i < 4; i++) {
            size_t off = (size_t)(b*N_ + n0 + i*256 + tid);
            px[i] = xyz[off*3+0];
            py[i] = xyz[off*3+1];
            pz[i] = xyz[off*3+2];
            pw[i] = (px[i]*px[i] + py[i]*py[i]) + pz[i]*pz[i];
        }
        float best[4] = {INFINITY, INFINITY, INFINITY, INFINITY};
        int   bi[4]   = {0, 0, 0, 0};
        #pragma unroll 2
        for (int s = 0; s < S_; s++) {
            float4 sd = s_seed[s];
            #pragma unroll
            for (int i = 0; i < 4; i++) {
                float d = px[i] * sd.x;
                d = fmaf(py[i], sd.y, d);
                d = fmaf(pz[i], sd.z, d);
                float d2 = (pw[i] + sd.w) - 2.0f*d;
                if (d2 < best[i]) { best[i] = d2; bi[i] = s; }  // first wins
            }
        }
        #pragma unroll
        for (int i = 0; i < 4; i++) {
            size_t off = (size_t)(b*N_ + n0 + i*256 + tid);
            g_assign[off] = bi[i];
            float4 f = ((const float4*)feat)[off];
            float* a = &s_acc[bi[i]*8];
            atomicAdd(a+0, px[i]); atomicAdd(a+1, py[i]); atomicAdd(a+2, pz[i]);
            atomicAdd(a+3, f.x);   atomicAdd(a+4, f.y);
            atomicAdd(a+5, f.z);   atomicAdd(a+6, f.w);
            atomicAdd(a+7, 1.0f);
        }
    }
    __syncthreads();

    int s  = tid;
    int bs = b*S_ + s;
    atomicAdd(&g_sumxyz [bs*3+0], s_acc[s*8+0]);
    atomicAdd(&g_sumxyz [bs*3+1], s_acc[s*8+1]);
    atomicAdd(&g_sumxyz [bs*3+2], s_acc[s*8+2]);
    atomicAdd(&g_sumfeat[bs*4+0], s_acc[s*8+3]);
    atomicAdd(&g_sumfeat[bs*4+1], s_acc[s*8+4]);
    atomicAdd(&g_sumfeat[bs*4+2], s_acc[s*8+5]);
    atomicAdd(&g_sumfeat[bs*4+3], s_acc[s*8+6]);
    atomicAdd(&g_cnt[bs],         s_acc[s*8+7]);
}

// ---------------- superpoint features -> token projection ----------
__global__ void tokens_kernel(const float* __restrict__ xyz,
                              const int*   __restrict__ seed_idx,
                              const float* __restrict__ pw,
                              const float* __restrict__ pb) {
    __shared__ float sp[7];
    int bs  = blockIdx.x;
    int b   = bs >> 8, s = bs & 255;
    int tid = threadIdx.x;
    if (tid == 0) {
        float cnt   = g_cnt[bs];
        float denom = fmaxf(cnt, 1.0f);
        bool  empty = (cnt == 0.0f);
        int   idx   = seed_idx[s];
        #pragma unroll
        for (int c = 0; c < 3; c++) {
            float seedc = xyz[(size_t)(b*N_ + idx)*3 + c];
            sp[c] = empty ? seedc : g_sumxyz[bs*3+c] / denom;
        }
        #pragma unroll
        for (int c = 0; c < 4; c++)
            sp[3+c] = empty ? 0.f : g_sumfeat[bs*4+c] / denom;
    }
    __syncthreads();
    float acc = 0.f;
    #pragma unroll
    for (int i = 0; i < 7; i++) acc = fmaf(sp[i], pw[tid*7 + i], acc);
    g_x[(size_t)bs*H_ + tid] = acc + pb[tid];
}

// ---------------- tensor-core GEMM (3xBF16, m16n8k16): C = epi(A@Wt + b) ---
// A: fp32, split in-kernel. W: PRE-SPLIT transposed bf16 hi/lo [K/2][Nw].
// 3 passes: al*bh + ah*bl + ah*bh (dropped lo*lo ~2^-18).
// KT=16, double-buffered, +8 pad => conflict-free fragment LDS.
// EPI: 0 = none, 1 = gelu, 2 = +residual
template<int TM, int TN, int WM, int WN, int THREADS, int MINCTA, int EPI>
__global__ void __launch_bounds__(THREADS, MINCTA)
sgemm_tc(const float* __restrict__ A,
         const uint32_t* __restrict__ Whi, const uint32_t* __restrict__ Wlo,
         const float* __restrict__ bias, const float* __restrict__ res,
         float* __restrict__ C, int M, int N, int K, int Nw) {
    constexpr int KT = 16;
    constexpr int PA = TM + 8;
    constexpr int PB = TN + 8;
    constexpr int WCOLS = TN / WN;
    constexpr int MT = WM / 16;
    constexpr int NT = WN / 8;
    constexpr int NLA = TM * 4 / THREADS;   // A float4 loads per thread
    constexpr int WU  = TN * 2 / THREADS;   // W uint4 loads per thread per array
    constexpr int C4  = TN / 4;             // uint4 per kpair row

    __shared__ __align__(16) uint32_t As_hi[2][8][PA];
    __shared__ __align__(16) uint32_t As_lo[2][8][PA];
    __shared__ __align__(16) uint32_t Ws_hi[2][8][PB];
    __shared__ __align__(16) uint32_t Ws_lo[2][8][PB];

    const int tid  = threadIdx.x;
    const int lane = tid & 31;
    const int wid  = tid >> 5;
    const int wrow = wid / WCOLS;
    const int wcol = wid % WCOLS;
    const int gr   = lane >> 2;          // 0..7
    const int ct   = lane & 3;           // 0..3
    const int bm   = blockIdx.y * TM;
    const int bn   = blockIdx.x * TN;

    float acc[MT][NT][4];
    #pragma unroll
    for (int mt = 0; mt < MT; mt++)
        #pragma unroll
        for (int nt = 0; nt < NT; nt++)
            #pragma unroll
            for (int j = 0; j < 4; j++) acc[mt][nt][j] = 0.f;

    float4 av[NLA];
    uint4  wh[WU], wl[WU];

    #pragma unroll
    for (int t = 0; t < NLA; t++) {
        int id = tid + t*THREADS, r = id >> 2, kq = id & 3;
        av[t] = *(const float4*)(A + (size_t)(bm + r)*K + kq*4);
    }
    #pragma unroll
    for (int t = 0; t < WU; t++) {
        int u = tid + t*THREADS, kp = u / C4, c4 = u % C4;
        size_t base = (size_t)kp*Nw + bn + c4*4;
        wh[t] = *(const uint4*)(Whi + base);
        wl[t] = *(const uint4*)(Wlo + base);
    }

    auto stage = [&](int buf) {
        #pragma unroll
        for (int t = 0; t < NLA; t++) {
            int id = tid + t*THREADS, r = id >> 2, kq = id & 3;
            uint32_t h0, l0, h1, l1;
            bf16_split2(av[t].x, av[t].y, h0, l0);
            bf16_split2(av[t].z, av[t].w, h1, l1);
            As_hi[buf][2*kq  ][r] = h0;
            As_hi[buf][2*kq+1][r] = h1;
            As_lo[buf][2*kq  ][r] = l0;
            As_lo[buf][2*kq+1][r] = l1;
        }
        #pragma unroll
        for (int t = 0; t < WU; t++) {
            int u = tid + t*THREADS, kp = u / C4, c4 = u % C4;
            *(uint4*)&Ws_hi[buf][kp][c4*4] = wh[t];
            *(uint4*)&Ws_lo[buf][kp][c4*4] = wl[t];
        }
    };

    stage(0);
    __syncthreads();

    const int nk = K / KT;
    for (int kt = 0; kt < nk; kt++) {
        const int buf = kt & 1;
        if (kt + 1 < nk) {
            int k0 = (kt + 1) * KT;
            #pragma unroll
            for (int t = 0; t < NLA; t++) {
                int id = tid + t*THREADS, r = id >> 2, kq = id & 3;
                av[t] = *(const float4*)(A + (size_t)(bm + r)*K + k0 + kq*4);
            }
            int kp0 = (kt + 1) * 8;
            #pragma unroll
            for (int t = 0; t < WU; t++) {
                int u = tid + t*THREADS, kp = u / C4, c4 = u % C4;
                size_t base = (size_t)(kp0 + kp)*Nw + bn + c4*4;
                wh[t] = *(const uint4*)(Whi + base);
                wl[t] = *(const uint4*)(Wlo + base);
            }
        }

        uint32_t ah[MT][4], al[MT][4];
        #pragma unroll
        for (int mt = 0; mt < MT; mt++) {
            int m = wrow*WM + mt*16 + gr;
            ah[mt][0] = As_hi[buf][ct  ][m];
            ah[mt][1] = As_hi[buf][ct  ][m + 8];
            ah[mt][2] = As_hi[buf][ct+4][m];
            ah[mt][3] = As_hi[buf][ct+4][m + 8];
            al[mt][0] = As_lo[buf][ct  ][m];
            al[mt][1] = As_lo[buf][ct  ][m + 8];
            al[mt][2] = As_lo[buf][ct+4][m];
            al[mt][3] = As_lo[buf][ct+4][m + 8];
        }
        #pragma unroll
        for (int nt = 0; nt < NT; nt++) {
            int n = wcol*WN + nt*8 + gr;
            uint32_t bh0 = Ws_hi[buf][ct  ][n];
            uint32_t bh1 = Ws_hi[buf][ct+4][n];
            uint32_t bl0 = Ws_lo[buf][ct  ][n];
            uint32_t bl1 = Ws_lo[buf][ct+4][n];
            #pragma unroll
            for (int mt = 0; mt < MT; mt++) {
                mma_bf16(acc[mt][nt], al[mt], bh0, bh1);   // lo*hi
                mma_bf16(acc[mt][nt], ah[mt], bl0, bl1);   // hi*lo
                mma_bf16(acc[mt][nt], ah[mt], bh0, bh1);   // hi*hi
            }
        }

        if (kt + 1 < nk) stage(buf ^ 1);
        __syncthreads();
    }

    // epilogue: C-frag m16n8: c0,c1 at (gr, ct*2..+1), c2,c3 at (gr+8, same)
    #pragma unroll
    for (int mt = 0; mt < MT; mt++) {
        int row = bm + wrow*WM + mt*16 + gr;
        #pragma unroll
        for (int nt = 0; nt < NT; nt++) {
            int col = bn + wcol*WN + nt*8 + ct*2;
            float b0 = bias[col], b1 = bias[col + 1];
            float c0 = acc[mt][nt][0] + b0;
            float c1 = acc[mt][nt][1] + b1;
            float c2 = acc[mt][nt][2] + b0;
            float c3 = acc[mt][nt][3] + b1;
            if (EPI == 1) {
                c0 = gelu_exact(c0); c1 = gelu_exact(c1);
                c2 = gelu_exact(c2); c3 = gelu_exact(c3);
            }
            if (EPI == 2) {
                float2 r0 = *(const float2*)(res + (size_t)row*N + col);
                float2 r1 = *(const float2*)(res + (size_t)(row + 8)*N + col);
                c0 += r0.x; c1 += r0.y; c2 += r1.x; c3 += r1.y;
            }
            *(float2*)(C + (size_t)row*N + col)       = make_float2(c0, c1);
            *(float2*)(C + (size_t)(row + 8)*N + col) = make_float2(c2, c3);
        }
    }
}

// ---------------- attention: split-K with in-warp merge ---------------------
// grid = B*NH*2 (query halves), 256 threads. Thread pair (2q, 2q+1) handles
// the SAME query over key halves [0,128) / [128,256); partial online-softmax
// states merge via shfl_xor(1) (partner always in-warp).
__global__ void attention_kernel(const float* __restrict__ qkv,
                                 float* __restrict__ outp) {
    __shared__ float Ks[S_][DH_];
    int bid  = blockIdx.x;
    int half = bid & 1;
    int bh   = bid >> 1;
    int b    = bh >> 3, h = bh & 7;
    int tid  = threadIdx.x;                 // 0..255
    const float* base = qkv + (size_t)b*S_*(3*H_);
    // 256 threads load 256 K rows (1 each)
    {
        const float4* kr = (const float4*)(base + (size_t)tid*(3*H_) + H_ + h*DH_);
        float4* dst = (float4*)&Ks[tid][0];
        #pragma unroll
        for (int i = 0; i < DH_/4; i++) dst[i] = kr[i];
    }
    int qlocal = tid >> 1;                  // 0..127
    int ks     = tid & 1;                   // key half
    int qrow   = half*128 + qlocal;
    float q[DH_];
    {
        const float4* qr = (const float4*)(base + (size_t)qrow*(3*H_) + h*DH_);
        #pragma unroll
        for (int i = 0; i < DH_/4; i++) ((float4*)q)[i] = qr[i];
    }
    __syncthreads();

    const float scale = 0.17677669529663688110f;   // 1/sqrt(32)
    float m = -INFINITY, l = 0.f;
    float acc[DH_];
    #pragma unroll
    for (int d = 0; d < DH_; d++) acc[d] = 0.f;
    const float* vbase = base + 2*H_ + h*DH_;
    const int j0 = ks * 128;

    for (int jj = 0; jj < 128; jj += 2) {
        int j = j0 + jj;
        float d0 = 0.f, d1 = 0.f, d2 = 0.f, d3 = 0.f;
        float e0 = 0.f, e1 = 0.f, e2 = 0.f, e3 = 0.f;
        #pragma unroll
        for (int i = 0; i < DH_/4; i++) {
            float4 k0 = ((const float4*)&Ks[j][0])[i];
            float4 k1 = ((const float4*)&Ks[j+1][0])[i];
            d0 = fmaf(q[4*i+0], k0.x, d0);
            d1 = fmaf(q[4*i+1], k0.y, d1);
            d2 = fmaf(q[4*i+2], k0.z, d2);
            d3 = fmaf(q[4*i+3], k0.w, d3);
            e0 = fmaf(q[4*i+0], k1.x, e0);
            e1 = fmaf(q[4*i+1], k1.y, e1);
            e2 = fmaf(q[4*i+2], k1.z, e2);
            e3 = fmaf(q[4*i+3], k1.w, e3);
        }
        float s0 = ((d0 + d1) + (d2 + d3)) * scale;
        float s1 = ((e0 + e1) + (e2 + e3)) * scale;
        float mn = fmaxf(m, fmaxf(s0, s1));
        float c  = __expf(m - mn);
        float p0 = __expf(s0 - mn);
        float p1 = __expf(s1 - mn);
        l = l*c + p0 + p1;
        const float4* v0 = (const float4*)(vbase + (size_t)j*(3*H_));
        const float4* v1 = (const float4*)(vbase + (size_t)(j+1)*(3*H_));
        #pragma unroll
        for (int i = 0; i < DH_/4; i++) {
            float4 a = v0[i], bq = v1[i];
            acc[i*4+0] = fmaf(acc[i*4+0], c, fmaf(p0, a.x, p1*bq.x));
            acc[i*4+1] = fmaf(acc[i*4+1], c, fmaf(p0, a.y, p1*bq.y));
            acc[i*4+2] = fmaf(acc[i*4+2], c, fmaf(p0, a.z, p1*bq.z));
            acc[i*4+3] = fmaf(acc[i*4+3], c, fmaf(p0, a.w, p1*bq.w));
        }
        m = mn;
    }

    // merge partial softmax state with partner lane (other key half)
    float mo = __shfl_xor_sync(0xffffffffu, m, 1);
    float lo = __shfl_xor_sync(0xffffffffu, l, 1);
    float mn = fmaxf(m, mo);
    float c1 = __expf(m  - mn);
    float c2 = __expf(mo - mn);
    float ltot = l*c1 + lo*c2;
    float inv = 1.0f / ltot;
    #pragma unroll
    for (int d = 0; d < DH_; d++) {
        float ao = __shfl_xor_sync(0xffffffffu, acc[d], 1);
        acc[d] = (acc[d]*c1 + ao*c2) * inv;
    }
    // both lanes hold the full result; each writes half (4 float4 each)
    float* orow = outp + (size_t)(b*S_ + qrow)*H_ + h*DH_ + ks*16;
    #pragma unroll
    for (int i = 0; i < 4; i++)
        ((float4*)orow)[i] = ((float4*)&acc[ks*16])[i];
}

// ---------------- layernorm: warp-per-row, barrier-free ----------
__global__ void layernorm_kernel(const float* __restrict__ in,
                                 const float* __restrict__ gw,
                                 const float* __restrict__ gb,
                                 float* __restrict__ outp) {
    int warp = threadIdx.x >> 5;
    int lane = threadIdx.x & 31;
    int row  = blockIdx.x * 8 + warp;
    const float4* in4 = (const float4*)in;
    float4 a = in4[(size_t)row*64 + lane*2];
    float4 b = in4[(size_t)row*64 + lane*2 + 1];
    float s1 = ((a.x + a.y) + (a.z + a.w)) + ((b.x + b.y) + (b.z + b.w));
    float s2 = ((a.x*a.x + a.y*a.y) + (a.z*a.z + a.w*a.w))
             + ((b.x*b.x + b.y*b.y) + (b.z*b.z + b.w*b.w));
    #pragma unroll
    for (int o = 16; o > 0; o >>= 1) {
        s1 += __shfl_xor_sync(0xffffffffu, s1, o);
        s2 += __shfl_xor_sync(0xffffffffu, s2, o);
    }
    float mean = s1 * (1.0f/H_);
    float var  = s2 * (1.0f/H_) - mean*mean;
    float rstd = rsqrtf(var + 1e-5f);
    float4 g0 = ((const float4*)gw)[lane*2];
    float4 g1 = ((const float4*)gw)[lane*2 + 1];
    float4 o0 = ((const float4*)gb)[lane*2];
    float4 o1 = ((const float4*)gb)[lane*2 + 1];
    float4 r0, r1;
    r0.x = (a.x - mean)*rstd*g0.x + o0.x;
    r0.y = (a.y - mean)*rstd*g0.y + o0.y;
    r0.z = (a.z - mean)*rstd*g0.z + o0.z;
    r0.w = (a.w - mean)*rstd*g0.w + o0.w;
    r1.x = (b.x - mean)*rstd*g1.x + o1.x;
    r1.y = (b.y - mean)*rstd*g1.y + o1.y;
    r1.z = (b.z - mean)*rstd*g1.z + o1.z;
    r1.w = (b.w - mean)*rstd*g1.w + o1.w;
    ((float4*)outp)[(size_t)row*64 + lane*2]     = r0;
    ((float4*)outp)[(size_t)row*64 + lane*2 + 1] = r1;
}

// ---------------- head2: logits (M x 13), one thread per output ----------
__global__ void head2_kernel(const float* __restrict__ X,
                             const float* __restrict__ W,
                             const float* __restrict__ bias) {
    int t = blockIdx.x * blockDim.x + threadIdx.x;
    if (t >= B_*S_*NC_) return;
    int row = t / NC_, c = t - row*NC_;
    const float4* x = (const float4*)(X + (size_t)row*H_);
    const float4* w = (const float4*)(W + (size_t)c*H_);
    float s0 = 0.f, s1 = 0.f, s2 = 0.f, s3 = 0.f;
    #pragma unroll 8
    for (int k = 0; k < H_/4; k++) {
        float4 xv = x[k], wv = w[k];
        s0 = fmaf(xv.x, wv.x, s0); s1 = fmaf(xv.y, wv.y, s1);
        s2 = fmaf(xv.z, wv.z, s2); s3 = fmaf(xv.w, wv.w, s3);
    }
    g_logits[t] = (s0+s1) + (s2+s3) + bias[c];
}

// ---------------- final gather to point logits ----------
__global__ void gather_kernel(float* __restrict__ out) {
    int t = blockIdx.x * blockDim.x + threadIdx.x;
    if (t >= B_*N_*NC_) return;
    int r = t / NC_;
    int c = t - r*NC_;
    int b = r >> 15;                // r / N_
    int a = g_assign[r];
    out[t] = g_logits[(b*S_ + a)*NC_ + c];
}

// ---------------- host launcher ----------
extern "C" void kernel_launch(void* const* d_in, const int* in_sizes, int n_in,
                              void* d_out, int out_size) {
    const float* xyz      = (const float*)d_in[0];
    const float* feat     = (const float*)d_in[1];
    const int*   seed_idx = (const int*)  d_in[2];
    const float* proj_w   = (const float*)d_in[3];
    const float* proj_b   = (const float*)d_in[4];
    const float* qkv_w    = (const float*)d_in[5];
    const float* qkv_b    = (const float*)d_in[6];
    const float* out_w    = (const float*)d_in[7];
    const float* out_b    = (const float*)d_in[8];
    const float* ln1_g    = (const float*)d_in[9];
    const float* ln1_b    = (const float*)d_in[10];
    const float* ln2_g    = (const float*)d_in[11];
    const float* ln2_b    = (const float*)d_in[12];
    const float* ff1_w    = (const float*)d_in[13];
    const float* ff1_b    = (const float*)d_in[14];
    const float* ff2_w    = (const float*)d_in[15];
    const float* ff2_b    = (const float*)d_in[16];
    const float* hln_g    = (const float*)d_in[17];
    const float* hln_b    = (const float*)d_in[18];
    const float* h1_w     = (const float*)d_in[19];
    const float* h1_b     = (const float*)d_in[20];
    const float* h2_w     = (const float*)d_in[21];
    const float* h2_b     = (const float*)d_in[22];
    float* out = (float*)d_out;

    float *p_x, *p_qkv, *p_attn, *p_tmp, *p_ff, *p_h1;
    uint32_t *p_Whi, *p_Wlo;
    cudaGetSymbolAddress((void**)&p_x,    g_x);
    cudaGetSymbolAddress((void**)&p_qkv,  g_qkv);
    cudaGetSymbolAddress((void**)&p_attn, g_attn);
    cudaGetSymbolAddress((void**)&p_tmp,  g_tmp);
    cudaGetSymbolAddress((void**)&p_ff,   g_ff);
    cudaGetSymbolAddress((void**)&p_h1,   g_h1);
    cudaGetSymbolAddress((void**)&p_Whi,  g_Whi);
    cudaGetSymbolAddress((void**)&p_Wlo,  g_Wlo);

    const int M = B_*S_;   // 4096

    split_all_kernel<<<(W_TOTAL + 255)/256, 256>>>(qkv_w, out_w, ff1_w,
                                                   ff2_w, h1_w);
    zero_kernel<<<(B_*S_*4 + 255)/256, 256>>>();
    assign_kernel<<<B_*16, 256>>>(xyz, feat, seed_idx);
    tokens_kernel<<<B_*S_, 256>>>(xyz, seed_idx, proj_w, proj_b);

    for (int l = 0; l < 2; l++) {
        // QKV: M=4096, N=768, K=256 -> 64x128 tiles, grid 6x64=384
        sgemm_tc<64,128,64,32,128,4,0><<<dim3(3*H_/128, M/64), 128>>>(
            p_x, p_Whi+OFF_QKV + l*98304, p_Wlo+OFF_QKV + l*98304,
            qkv_b + l*3*H_, nullptr, p_qkv, M, 3*H_, H_, 768);
        attention_kernel<<<B_*NH_*2, 256>>>(p_qkv, p_attn);
        // out-proj: N=256, K=256 -> 64x64 tiles, grid 4x64=256, +residual
        sgemm_tc<64,64,32,32,128,4,2><<<dim3(H_/64, M/64), 128>>>(
            p_attn, p_Whi+OFF_OUT + l*32768, p_Wlo+OFF_OUT + l*32768,
            out_b + l*H_, p_x, p_tmp, M, H_, H_, 256);
        layernorm_kernel<<<M/8, 256>>>(p_tmp, ln1_g + l*H_, ln1_b + l*H_, p_x);
        // FF1: N=1024, K=256 -> 64x128 tiles, grid 8x64=512, gelu
        sgemm_tc<64,128,64,32,128,4,1><<<dim3(DFF_/128, M/64), 128>>>(
            p_x, p_Whi+OFF_FF1 + l*131072, p_Wlo+OFF_FF1 + l*131072,
            ff1_b + l*DFF_, nullptr, p_ff, M, DFF_, H_, 1024);
        // FF2: N=256, K=1024 -> 64x64 tiles, +residual
        sgemm_tc<64,64,32,32,128,4,2><<<dim3(H_/64, M/64), 128>>>(
            p_ff, p_Whi+OFF_FF2 + l*131072, p_Wlo+OFF_FF2 + l*131072,
            ff2_b + l*H_, p_x, p_tmp, M, H_, DFF_, 256);
        layernorm_kernel<<<M/8, 256>>>(p_tmp, ln2_g + l*H_, ln2_b + l*H_, p_x);
    }

    layernorm_kernel<<<M/8, 256>>>(p_x, hln_g, hln_b, p_tmp);
    sgemm_tc<64,64,32,32,128,4,1><<<dim3(H_/64, M/64), 128>>>(
        p_tmp, p_Whi+OFF_H1, p_Wlo+OFF_H1, h1_b, nullptr, p_h1,
        M, H_, H_, 256);
    head2_kernel<<<(M*NC_ + 255)/256, 256>>>(p_h1, h2_w, h2_b);
    gather_kernel<<<(B_*N_*NC_ + 255)/256, 256>>>(out);
}

// round 13
// speedup vs baseline: 1.3896x; 1.0035x over previous
#include <cuda_runtime.h>
#include <cuda_bf16.h>
#include <math.h>
#include <stdint.h>

#define B_   16
#define N_   32768
#define S_   256
#define H_   256
#define NH_  8
#define DH_  32
#define DFF_ 1024
#define NC_  13

// pre-split transposed weight pool offsets (uint32 elements)
#define OFF_QKV 0
#define OFF_OUT 196608
#define OFF_FF1 262144
#define OFF_FF2 524288
#define OFF_H1  786432
#define W_TOTAL 819200

// ---------------- scratch (device globals; no allocations allowed) ----------
__device__ float g_sumxyz[B_*S_*3];
__device__ float g_sumfeat[B_*S_*4];
__device__ float g_cnt[B_*S_];
__device__ int   g_assign[B_*N_];
__device__ float g_x[B_*S_*H_];
__device__ float g_qkv[B_*S_*3*H_];
__device__ float g_attn[B_*S_*H_];
__device__ float g_tmp[B_*S_*H_];
__device__ float g_ff[B_*S_*DFF_];
__device__ float g_h1[B_*S_*H_];
__device__ float g_logits[B_*S_*NC_];
__device__ uint32_t g_Whi[W_TOTAL];
__device__ uint32_t g_Wlo[W_TOTAL];

// ---------------- utils ----------
__device__ __forceinline__ float gelu_exact(float x) {
    return 0.5f * x * (1.0f + erff(x * 0.70710678118654752440f));
}

// split a float2 into packed bf16x2 hi and lo: x = hi + lo + O(2^-18 x)
__device__ __forceinline__ void bf16_split2(float fx, float fy,
                                            uint32_t& hi, uint32_t& lo) {
    __nv_bfloat162 h = __float22bfloat162_rn(make_float2(fx, fy));
    hi = *(uint32_t*)&h;
    float2 hf = __bfloat1622float2(h);
    __nv_bfloat162 l = __float22bfloat162_rn(make_float2(fx - hf.x, fy - hf.y));
    lo = *(uint32_t*)&l;
}

__device__ __forceinline__ void mma_bf16(float* d, const uint32_t* a,
                                         uint32_t b0, uint32_t b1) {
    asm volatile(
        "mma.sync.aligned.m16n8k16.row.col.f32.bf16.bf16.f32 "
        "{%0,%1,%2,%3},{%4,%5,%6,%7},{%8,%9},{%0,%1,%2,%3};"
        : "+f"(d[0]), "+f"(d[1]), "+f"(d[2]), "+f"(d[3])
        : "r"(a[0]), "r"(a[1]), "r"(a[2]), "r"(a[3]), "r"(b0), "r"(b1));
}

// ---------------- merged weight split + transpose + accumulator zero -------
// W[N][K] -> hi/lo [K/2][N] per layer, 5 regions dispatched by global id.
// Also zeroes the segment accumulators (runs before assign_kernel).
__global__ void split_all_kernel(const float* __restrict__ qkv_w,
                                 const float* __restrict__ out_w,
                                 const float* __restrict__ ff1_w,
                                 const float* __restrict__ ff2_w,
                                 const float* __restrict__ h1_w) {
    int id = blockIdx.x * blockDim.x + threadIdx.x;
    if (id < B_*S_*3) g_sumxyz[id]  = 0.f;
    if (id < B_*S_*4) g_sumfeat[id] = 0.f;
    if (id < B_*S_)   g_cnt[id]     = 0.f;
    if (id >= W_TOTAL) return;
    const float* src; int Nw, Kp, off, lsS, lsD, rel;
    if (id < 262144) {
        if (id < 196608) { src=qkv_w; Nw=768;  Kp=128; off=OFF_QKV; lsS=196608; lsD=98304;  rel=id; }
        else             { src=out_w; Nw=256;  Kp=128; off=OFF_OUT; lsS=65536;  lsD=32768;  rel=id-196608; }
    } else if (id < 524288) {
        src=ff1_w; Nw=1024; Kp=128; off=OFF_FF1; lsS=262144; lsD=131072; rel=id-262144;
    } else if (id < 786432) {
        src=ff2_w; Nw=256;  Kp=512; off=OFF_FF2; lsS=262144; lsD=131072; rel=id-524288;
    } else {
        src=h1_w;  Nw=256;  Kp=128; off=OFF_H1;  lsS=0;      lsD=0;      rel=id-786432;
    }
    int l   = rel / (Kp * Nw);
    int r2  = rel - l * (Kp * Nw);
    int n   = r2 / Kp;
    int kp  = r2 - n * Kp;
    const float* s = src + (size_t)l*lsS + (size_t)n*(2*Kp) + 2*kp;
    uint32_t h, lw;
    bf16_split2(s[0], s[1], h, lw);
    size_t d = (size_t)off + (size_t)l*lsD + (size_t)kp*Nw + n;
    g_Whi[d] = h;
    g_Wlo[d] = lw;
}

// ---------------- point -> seed argmin + block-local segment sums ----------
__global__ void assign_kernel(const float* __restrict__ xyz,
                              const float* __restrict__ feat,
                              const int*   __restrict__ seed_idx) {
    __shared__ float4 s_seed[S_];
    __shared__ float s_acc[S_*8];
    int b     = blockIdx.x >> 4;
    int chunk = blockIdx.x & 15;
    int tid   = threadIdx.x;

    {
        int idx = seed_idx[tid];
        float a0 = xyz[(size_t)(b*N_ + idx)*3 + 0];
        float a1 = xyz[(size_t)(b*N_ + idx)*3 + 1];
        float a2 = xyz[(size_t)(b*N_ + idx)*3 + 2];
        s_seed[tid] = make_float4(a0, a1, a2, (a0*a0 + a1*a1) + a2*a2);
    }
    #pragma unroll
    for (int i = 0; i < 8; i++) s_acc[tid + i*256] = 0.f;
    __syncthreads();

    for (int pp = 0; pp < 2; pp++) {
        int n0 = chunk*2048 + pp*1024;
        float px[4], py[4], pz[4], pw[4];
        #pragma unroll
        for (int i = 0; i < 4; i++) {
            size_t off = (size_t)(b*N_ + n0 + i*256 + tid);
            px[i] = xyz[off*3+0];
            py[i] = xyz[off*3+1];
            pz[i] = xyz[off*3+2];
            pw[i] = (px[i]*px[i] + py[i]*py[i]) + pz[i]*pz[i];
        }
        float best[4] = {INFINITY, INFINITY, INFINITY, INFINITY};
        int   bi[4]   = {0, 0, 0, 0};
        #pragma unroll 2
        for (int s = 0; s < S_; s++) {
            float4 sd = s_seed[s];
            #pragma unroll
            for (int i = 0; i < 4; i++) {
                float d = px[i] * sd.x;
                d = fmaf(py[i], sd.y, d);
                d = fmaf(pz[i], sd.z, d);
                float d2 = (pw[i] + sd.w) - 2.0f*d;
                if (d2 < best[i]) { best[i] = d2; bi[i] = s; }  // first wins
            }
        }
        #pragma unroll
        for (int i = 0; i < 4; i++) {
            size_t off = (size_t)(b*N_ + n0 + i*256 + tid);
            g_assign[off] = bi[i];
            float4 f = ((const float4*)feat)[off];
            float* a = &s_acc[bi[i]*8];
            atomicAdd(a+0, px[i]); atomicAdd(a+1, py[i]); atomicAdd(a+2, pz[i]);
            atomicAdd(a+3, f.x);   atomicAdd(a+4, f.y);
            atomicAdd(a+5, f.z);   atomicAdd(a+6, f.w);
            atomicAdd(a+7, 1.0f);
        }
    }
    __syncthreads();

    int s  = tid;
    int bs = b*S_ + s;
    atomicAdd(&g_sumxyz [bs*3+0], s_acc[s*8+0]);
    atomicAdd(&g_sumxyz [bs*3+1], s_acc[s*8+1]);
    atomicAdd(&g_sumxyz [bs*3+2], s_acc[s*8+2]);
    atomicAdd(&g_sumfeat[bs*4+0], s_acc[s*8+3]);
    atomicAdd(&g_sumfeat[bs*4+1], s_acc[s*8+4]);
    atomicAdd(&g_sumfeat[bs*4+2], s_acc[s*8+5]);
    atomicAdd(&g_sumfeat[bs*4+3], s_acc[s*8+6]);
    atomicAdd(&g_cnt[bs],         s_acc[s*8+7]);
}

// ---------------- superpoint features -> token projection ----------
// 512 blocks x 8 rows: sp vectors computed in parallel (thread (r,c) -> one
// element), one barrier, then each thread emits its channel for all 8 rows.
__global__ void tokens_kernel(const float* __restrict__ xyz,
                              const int*   __restrict__ seed_idx,
                              const float* __restrict__ pw,
                              const float* __restrict__ pb) {
    __shared__ float sp[8][8];
    int tid = threadIdx.x;
    int blk = blockIdx.x;            // 0..511
    if (tid < 64) {
        int r = tid >> 3, c = tid & 7;
        if (c < 7) {
            int bs = blk*8 + r;
            int b = bs >> 8, s = bs & 255;
            float cnt   = g_cnt[bs];
            float denom = fmaxf(cnt, 1.0f);
            bool  empty = (cnt == 0.0f);
            float v;
            if (c < 3) {
                int idx = seed_idx[s];
                float seedc = xyz[(size_t)(b*N_ + idx)*3 + c];
                v = empty ? seedc : g_sumxyz[bs*3 + c] / denom;
            } else {
                v = empty ? 0.f : g_sumfeat[bs*4 + (c - 3)] / denom;
            }
            sp[r][c] = v;
        }
    }
    float w[7];
    #pragma unroll
    for (int i = 0; i < 7; i++) w[i] = pw[tid*7 + i];
    float bb = pb[tid];
    __syncthreads();
    #pragma unroll
    for (int r = 0; r < 8; r++) {
        float acc = 0.f;
        #pragma unroll
        for (int i = 0; i < 7; i++) acc = fmaf(sp[r][i], w[i], acc);
        g_x[(size_t)(blk*8 + r)*H_ + tid] = acc + bb;
    }
}

// ---------------- tensor-core GEMM (3xBF16, m16n8k16): C = epi(A@Wt + b) ---
// A: fp32, split in-kernel. W: PRE-SPLIT transposed bf16 hi/lo [K/2][Nw].
// 3 passes: al*bh + ah*bl + ah*bh (dropped lo*lo ~2^-18).
// KT=16, double-buffered, +8 pad => conflict-free fragment LDS.
// EPI: 0 = none, 1 = gelu, 2 = +residual
template<int TM, int TN, int WM, int WN, int THREADS, int MINCTA, int EPI>
__global__ void __launch_bounds__(THREADS, MINCTA)
sgemm_tc(const float* __restrict__ A,
         const uint32_t* __restrict__ Whi, const uint32_t* __restrict__ Wlo,
         const float* __restrict__ bias, const float* __restrict__ res,
         float* __restrict__ C, int M, int N, int K, int Nw) {
    constexpr int KT = 16;
    constexpr int PA = TM + 8;
    constexpr int PB = TN + 8;
    constexpr int WCOLS = TN / WN;
    constexpr int MT = WM / 16;
    constexpr int NT = WN / 8;
    constexpr int NLA = TM * 4 / THREADS;   // A float4 loads per thread
    constexpr int WU  = TN * 2 / THREADS;   // W uint4 loads per thread per array
    constexpr int C4  = TN / 4;             // uint4 per kpair row

    __shared__ __align__(16) uint32_t As_hi[2][8][PA];
    __shared__ __align__(16) uint32_t As_lo[2][8][PA];
    __shared__ __align__(16) uint32_t Ws_hi[2][8][PB];
    __shared__ __align__(16) uint32_t Ws_lo[2][8][PB];

    const int tid  = threadIdx.x;
    const int lane = tid & 31;
    const int wid  = tid >> 5;
    const int wrow = wid / WCOLS;
    const int wcol = wid % WCOLS;
    const int gr   = lane >> 2;          // 0..7
    const int ct   = lane & 3;           // 0..3
    const int bm   = blockIdx.y * TM;
    const int bn   = blockIdx.x * TN;

    float acc[MT][NT][4];
    #pragma unroll
    for (int mt = 0; mt < MT; mt++)
        #pragma unroll
        for (int nt = 0; nt < NT; nt++)
            #pragma unroll
            for (int j = 0; j < 4; j++) acc[mt][nt][j] = 0.f;

    float4 av[NLA];
    uint4  wh[WU], wl[WU];

    #pragma unroll
    for (int t = 0; t < NLA; t++) {
        int id = tid + t*THREADS, r = id >> 2, kq = id & 3;
        av[t] = *(const float4*)(A + (size_t)(bm + r)*K + kq*4);
    }
    #pragma unroll
    for (int t = 0; t < WU; t++) {
        int u = tid + t*THREADS, kp = u / C4, c4 = u % C4;
        size_t base = (size_t)kp*Nw + bn + c4*4;
        wh[t] = *(const uint4*)(Whi + base);
        wl[t] = *(const uint4*)(Wlo + base);
    }

    auto stage = [&](int buf) {
        #pragma unroll
        for (int t = 0; t < NLA; t++) {
            int id = tid + t*THREADS, r = id >> 2, kq = id & 3;
            uint32_t h0, l0, h1, l1;
            bf16_split2(av[t].x, av[t].y, h0, l0);
            bf16_split2(av[t].z, av[t].w, h1, l1);
            As_hi[buf][2*kq  ][r] = h0;
            As_hi[buf][2*kq+1][r] = h1;
            As_lo[buf][2*kq  ][r] = l0;
            As_lo[buf][2*kq+1][r] = l1;
        }
        #pragma unroll
        for (int t = 0; t < WU; t++) {
            int u = tid + t*THREADS, kp = u / C4, c4 = u % C4;
            *(uint4*)&Ws_hi[buf][kp][c4*4] = wh[t];
            *(uint4*)&Ws_lo[buf][kp][c4*4] = wl[t];
        }
    };

    stage(0);
    __syncthreads();

    const int nk = K / KT;
    for (int kt = 0; kt < nk; kt++) {
        const int buf = kt & 1;
        if (kt + 1 < nk) {
            int k0 = (kt + 1) * KT;
            #pragma unroll
            for (int t = 0; t < NLA; t++) {
                int id = tid + t*THREADS, r = id >> 2, kq = id & 3;
                av[t] = *(const float4*)(A + (size_t)(bm + r)*K + k0 + kq*4);
            }
            int kp0 = (kt + 1) * 8;
            #pragma unroll
            for (int t = 0; t < WU; t++) {
                int u = tid + t*THREADS, kp = u / C4, c4 = u % C4;
                size_t base = (size_t)(kp0 + kp)*Nw + bn + c4*4;
                wh[t] = *(const uint4*)(Whi + base);
                wl[t] = *(const uint4*)(Wlo + base);
            }
        }

        uint32_t ah[MT][4], al[MT][4];
        #pragma unroll
        for (int mt = 0; mt < MT; mt++) {
            int m = wrow*WM + mt*16 + gr;
            ah[mt][0] = As_hi[buf][ct  ][m];
            ah[mt][1] = As_hi[buf][ct  ][m + 8];
            ah[mt][2] = As_hi[buf][ct+4][m];
            ah[mt][3] = As_hi[buf][ct+4][m + 8];
            al[mt][0] = As_lo[buf][ct  ][m];
            al[mt][1] = As_lo[buf][ct  ][m + 8];
            al[mt][2] = As_lo[buf][ct+4][m];
            al[mt][3] = As_lo[buf][ct+4][m + 8];
        }
        #pragma unroll
        for (int nt = 0; nt < NT; nt++) {
            int n = wcol*WN + nt*8 + gr;
            uint32_t bh0 = Ws_hi[buf][ct  ][n];
            uint32_t bh1 = Ws_hi[buf][ct+4][n];
            uint32_t bl0 = Ws_lo[buf][ct  ][n];
            uint32_t bl1 = Ws_lo[buf][ct+4][n];
            #pragma unroll
            for (int mt = 0; mt < MT; mt++) {
                mma_bf16(acc[mt][nt], al[mt], bh0, bh1);   // lo*hi
                mma_bf16(acc[mt][nt], ah[mt], bl0, bl1);   // hi*lo
                mma_bf16(acc[mt][nt], ah[mt], bh0, bh1);   // hi*hi
            }
        }

        if (kt + 1 < nk) stage(buf ^ 1);
        __syncthreads();
    }

    // epilogue: C-frag m16n8: c0,c1 at (gr, ct*2..+1), c2,c3 at (gr+8, same)
    #pragma unroll
    for (int mt = 0; mt < MT; mt++) {
        int row = bm + wrow*WM + mt*16 + gr;
        #pragma unroll
        for (int nt = 0; nt < NT; nt++) {
            int col = bn + wcol*WN + nt*8 + ct*2;
            float b0 = bias[col], b1 = bias[col + 1];
            float c0 = acc[mt][nt][0] + b0;
            float c1 = acc[mt][nt][1] + b1;
            float c2 = acc[mt][nt][2] + b0;
            float c3 = acc[mt][nt][3] + b1;
            if (EPI == 1) {
                c0 = gelu_exact(c0); c1 = gelu_exact(c1);
                c2 = gelu_exact(c2); c3 = gelu_exact(c3);
            }
            if (EPI == 2) {
                float2 r0 = *(const float2*)(res + (size_t)row*N + col);
                float2 r1 = *(const float2*)(res + (size_t)(row + 8)*N + col);
                c0 += r0.x; c1 += r0.y; c2 += r1.x; c3 += r1.y;
            }
            *(float2*)(C + (size_t)row*N + col)       = make_float2(c0, c1);
            *(float2*)(C + (size_t)(row + 8)*N + col) = make_float2(c2, c3);
        }
    }
}

// ---------------- attention: split-K with in-warp merge ---------------------
// grid = B*NH*2 (query halves), 256 threads. Thread pair (2q, 2q+1) handles
// the SAME query over key halves [0,128) / [128,256); partial online-softmax
// states merge via shfl_xor(1) (partner always in-warp).
__global__ void attention_kernel(const float* __restrict__ qkv,
                                 float* __restrict__ outp) {
    __shared__ float Ks[S_][DH_];
    int bid  = blockIdx.x;
    int half = bid & 1;
    int bh   = bid >> 1;
    int b    = bh >> 3, h = bh & 7;
    int tid  = threadIdx.x;                 // 0..255
    const float* base = qkv + (size_t)b*S_*(3*H_);
    {
        const float4* kr = (const float4*)(base + (size_t)tid*(3*H_) + H_ + h*DH_);
        float4* dst = (float4*)&Ks[tid][0];
        #pragma unroll
        for (int i = 0; i < DH_/4; i++) dst[i] = kr[i];
    }
    int qlocal = tid >> 1;                  // 0..127
    int ks     = tid & 1;                   // key half
    int qrow   = half*128 + qlocal;
    float q[DH_];
    {
        const float4* qr = (const float4*)(base + (size_t)qrow*(3*H_) + h*DH_);
        #pragma unroll
        for (int i = 0; i < DH_/4; i++) ((float4*)q)[i] = qr[i];
    }
    __syncthreads();

    const float scale = 0.17677669529663688110f;   // 1/sqrt(32)
    float m = -INFINITY, l = 0.f;
    float acc[DH_];
    #pragma unroll
    for (int d = 0; d < DH_; d++) acc[d] = 0.f;
    const float* vbase = base + 2*H_ + h*DH_;
    const int j0 = ks * 128;

    for (int jj = 0; jj < 128; jj += 2) {
        int j = j0 + jj;
        float d0 = 0.f, d1 = 0.f, d2 = 0.f, d3 = 0.f;
        float e0 = 0.f, e1 = 0.f, e2 = 0.f, e3 = 0.f;
        #pragma unroll
        for (int i = 0; i < DH_/4; i++) {
            float4 k0 = ((const float4*)&Ks[j][0])[i];
            float4 k1 = ((const float4*)&Ks[j+1][0])[i];
            d0 = fmaf(q[4*i+0], k0.x, d0);
            d1 = fmaf(q[4*i+1], k0.y, d1);
            d2 = fmaf(q[4*i+2], k0.z, d2);
            d3 = fmaf(q[4*i+3], k0.w, d3);
            e0 = fmaf(q[4*i+0], k1.x, e0);
            e1 = fmaf(q[4*i+1], k1.y, e1);
            e2 = fmaf(q[4*i+2], k1.z, e2);
            e3 = fmaf(q[4*i+3], k1.w, e3);
        }
        float s0 = ((d0 + d1) + (d2 + d3)) * scale;
        float s1 = ((e0 + e1) + (e2 + e3)) * scale;
        float mn = fmaxf(m, fmaxf(s0, s1));
        float c  = __expf(m - mn);
        float p0 = __expf(s0 - mn);
        float p1 = __expf(s1 - mn);
        l = l*c + p0 + p1;
        const float4* v0 = (const float4*)(vbase + (size_t)j*(3*H_));
        const float4* v1 = (const float4*)(vbase + (size_t)(j+1)*(3*H_));
        #pragma unroll
        for (int i = 0; i < DH_/4; i++) {
            float4 a = v0[i], bq = v1[i];
            acc[i*4+0] = fmaf(acc[i*4+0], c, fmaf(p0, a.x, p1*bq.x));
            acc[i*4+1] = fmaf(acc[i*4+1], c, fmaf(p0, a.y, p1*bq.y));
            acc[i*4+2] = fmaf(acc[i*4+2], c, fmaf(p0, a.z, p1*bq.z));
            acc[i*4+3] = fmaf(acc[i*4+3], c, fmaf(p0, a.w, p1*bq.w));
        }
        m = mn;
    }

    // merge partial softmax state with partner lane (other key half)
    float mo = __shfl_xor_sync(0xffffffffu, m, 1);
    float lo = __shfl_xor_sync(0xffffffffu, l, 1);
    float mn = fmaxf(m, mo);
    float c1 = __expf(m  - mn);
    float c2 = __expf(mo - mn);
    float ltot = l*c1 + lo*c2;
    float inv = 1.0f / ltot;
    #pragma unroll
    for (int d = 0; d < DH_; d++) {
        float ao = __shfl_xor_sync(0xffffffffu, acc[d], 1);
        acc[d] = (acc[d]*c1 + ao*c2) * inv;
    }
    // both lanes hold the full result; each writes half (4 float4 each)
    float* orow = outp + (size_t)(b*S_ + qrow)*H_ + h*DH_ + ks*16;
    #pragma unroll
    for (int i = 0; i < 4; i++)
        ((float4*)orow)[i] = ((float4*)&acc[ks*16])[i];
}

// ---------------- layernorm: warp-per-row, barrier-free ----------
__global__ void layernorm_kernel(const float* __restrict__ in,
                                 const float* __restrict__ gw,
                                 const float* __restrict__ gb,
                                 float* __restrict__ outp) {
    int warp = threadIdx.x >> 5;
    int lane = threadIdx.x & 31;
    int row  = blockIdx.x * 8 + warp;
    const float4* in4 = (const float4*)in;
    float4 a = in4[(size_t)row*64 + lane*2];
    float4 b = in4[(size_t)row*64 + lane*2 + 1];
    float s1 = ((a.x + a.y) + (a.z + a.w)) + ((b.x + b.y) + (b.z + b.w));
    float s2 = ((a.x*a.x + a.y*a.y) + (a.z*a.z + a.w*a.w))
             + ((b.x*b.x + b.y*b.y) + (b.z*b.z + b.w*b.w));
    #pragma unroll
    for (int o = 16; o > 0; o >>= 1) {
        s1 += __shfl_xor_sync(0xffffffffu, s1, o);
        s2 += __shfl_xor_sync(0xffffffffu, s2, o);
    }
    float mean = s1 * (1.0f/H_);
    float var  = s2 * (1.0f/H_) - mean*mean;
    float rstd = rsqrtf(var + 1e-5f);
    float4 g0 = ((const float4*)gw)[lane*2];
    float4 g1 = ((const float4*)gw)[lane*2 + 1];
    float4 o0 = ((const float4*)gb)[lane*2];
    float4 o1 = ((const float4*)gb)[lane*2 + 1];
    float4 r0, r1;
    r0.x = (a.x - mean)*rstd*g0.x + o0.x;
    r0.y = (a.y - mean)*rstd*g0.y + o0.y;
    r0.z = (a.z - mean)*rstd*g0.z + o0.z;
    r0.w = (a.w - mean)*rstd*g0.w + o0.w;
    r1.x = (b.x - mean)*rstd*g1.x + o1.x;
    r1.y = (b.y - mean)*rstd*g1.y + o1.y;
    r1.z = (b.z - mean)*rstd*g1.z + o1.z;
    r1.w = (b.w - mean)*rstd*g1.w + o1.w;
    ((float4*)outp)[(size_t)row*64 + lane*2]     = r0;
    ((float4*)outp)[(size_t)row*64 + lane*2 + 1] = r1;
}

// ---------------- head2: logits (M x 13), one thread per output ----------
__global__ void head2_kernel(const float* __restrict__ X,
                             const float* __restrict__ W,
                             const float* __restrict__ bias) {
    int t = blockIdx.x * blockDim.x + threadIdx.x;
    if (t >= B_*S_*NC_) return;
    int row = t / NC_, c = t - row*NC_;
    const float4* x = (const float4*)(X + (size_t)row*H_);
    const float4* w = (const float4*)(W + (size_t)c*H_);
    float s0 = 0.f, s1 = 0.f, s2 = 0.f, s3 = 0.f;
    #pragma unroll 8
    for (int k = 0; k < H_/4; k++) {
        float4 xv = x[k], wv = w[k];
        s0 = fmaf(xv.x, wv.x, s0); s1 = fmaf(xv.y, wv.y, s1);
        s2 = fmaf(xv.z, wv.z, s2); s3 = fmaf(xv.w, wv.w, s3);
    }
    g_logits[t] = (s0+s1) + (s2+s3) + bias[c];
}

// ---------------- final gather to point logits ----------
__global__ void gather_kernel(float* __restrict__ out) {
    int t = blockIdx.x * blockDim.x + threadIdx.x;
    if (t >= B_*N_*NC_) return;
    int r = t / NC_;
    int c = t - r*NC_;
    int b = r >> 15;                // r / N_
    int a = g_assign[r];
    out[t] = g_logits[(b*S_ + a)*NC_ + c];
}

// ---------------- host launcher ----------
extern "C" void kernel_launch(void* const* d_in, const int* in_sizes, int n_in,
                              void* d_out, int out_size) {
    const float* xyz      = (const float*)d_in[0];
    const float* feat     = (const float*)d_in[1];
    const int*   seed_idx = (const int*)  d_in[2];
    const float* proj_w   = (const float*)d_in[3];
    const float* proj_b   = (const float*)d_in[4];
    const float* qkv_w    = (const float*)d_in[5];
    const float* qkv_b    = (const float*)d_in[6];
    const float* out_w    = (const float*)d_in[7];
    const float* out_b    = (const float*)d_in[8];
    const float* ln1_g    = (const float*)d_in[9];
    const float* ln1_b    = (const float*)d_in[10];
    const float* ln2_g    = (const float*)d_in[11];
    const float* ln2_b    = (const float*)d_in[12];
    const float* ff1_w    = (const float*)d_in[13];
    const float* ff1_b    = (const float*)d_in[14];
    const float* ff2_w    = (const float*)d_in[15];
    const float* ff2_b    = (const float*)d_in[16];
    const float* hln_g    = (const float*)d_in[17];
    const float* hln_b    = (const float*)d_in[18];
    const float* h1_w     = (const float*)d_in[19];
    const float* h1_b     = (const float*)d_in[20];
    const float* h2_w     = (const float*)d_in[21];
    const float* h2_b     = (const float*)d_in[22];
    float* out = (float*)d_out;

    float *p_x, *p_qkv, *p_attn, *p_tmp, *p_ff, *p_h1;
    uint32_t *p_Whi, *p_Wlo;
    cudaGetSymbolAddress((void**)&p_x,    g_x);
    cudaGetSymbolAddress((void**)&p_qkv,  g_qkv);
    cudaGetSymbolAddress((void**)&p_attn, g_attn);
    cudaGetSymbolAddress((void**)&p_tmp,  g_tmp);
    cudaGetSymbolAddress((void**)&p_ff,   g_ff);
    cudaGetSymbolAddress((void**)&p_h1,   g_h1);
    cudaGetSymbolAddress((void**)&p_Whi,  g_Whi);
    cudaGetSymbolAddress((void**)&p_Wlo,  g_Wlo);

    const int M = B_*S_;   // 4096

    split_all_kernel<<<(W_TOTAL + 255)/256, 256>>>(qkv_w, out_w, ff1_w,
                                                   ff2_w, h1_w);
    assign_kernel<<<B_*16, 256>>>(xyz, feat, seed_idx);
    tokens_kernel<<<M/8, 256>>>(xyz, seed_idx, proj_w, proj_b);

    for (int l = 0; l < 2; l++) {
        // QKV: M=4096, N=768, K=256 -> 64x128 tiles, grid 6x64=384
        sgemm_tc<64,128,64,32,128,4,0><<<dim3(3*H_/128, M/64), 128>>>(
            p_x, p_Whi+OFF_QKV + l*98304, p_Wlo+OFF_QKV + l*98304,
            qkv_b + l*3*H_, nullptr, p_qkv, M, 3*H_, H_, 768);
        attention_kernel<<<B_*NH_*2, 256>>>(p_qkv, p_attn);
        // out-proj: N=256, K=256 -> 64x64 tiles, grid 4x64=256, +residual
        sgemm_tc<64,64,32,32,128,4,2><<<dim3(H_/64, M/64), 128>>>(
            p_attn, p_Whi+OFF_OUT + l*32768, p_Wlo+OFF_OUT + l*32768,
            out_b + l*H_, p_x, p_tmp, M, H_, H_, 256);
        layernorm_kernel<<<M/8, 256>>>(p_tmp, ln1_g + l*H_, ln1_b + l*H_, p_x);
        // FF1: N=1024, K=256 -> 64x128 tiles, grid 8x64=512, gelu
        sgemm_tc<64,128,64,32,128,4,1><<<dim3(DFF_/128, M/64), 128>>>(
            p_x, p_Whi+OFF_FF1 + l*131072, p_Wlo+OFF_FF1 + l*131072,
            ff1_b + l*DFF_, nullptr, p_ff, M, DFF_, H_, 1024);
        // FF2: N=256, K=1024 -> 64x64 tiles, +residual
        sgemm_tc<64,64,32,32,128,4,2><<<dim3(H_/64, M/64), 128>>>(
            p_ff, p_Whi+OFF_FF2 + l*131072, p_Wlo+OFF_FF2 + l*131072,
            ff2_b + l*H_, p_x, p_tmp, M, H_, DFF_, 256);
        layernorm_kernel<<<M/8, 256>>>(p_tmp, ln2_g + l*H_, ln2_b + l*H_, p_x);
    }

    layernorm_kernel<<<M/8, 256>>>(p_x, hln_g, hln_b, p_tmp);
    sgemm_tc<64,64,32,32,128,4,1><<<dim3(H_/64, M/64), 128>>>(
        p_tmp, p_Whi+OFF_H1, p_Wlo+OFF_H1, h1_b, nullptr, p_h1,
        M, H_, H_, 256);
    head2_kernel<<<(M*NC_ + 255)/256, 256>>>(p_h1, h2_w, h2_b);
    gather_kernel<<<(B_*N_*NC_ + 255)/256, 256>>>(out);
}